// round 3
// baseline (speedup 1.0000x reference)
#include <cuda_runtime.h>
#include <math.h>

// Problem constants
#define BATCH 32
#define SEQT  1024
#define CDIM  512
#define LRAW  252
#define SLEN  128
#define MTOK  (BATCH * SEQT)   // 32768
#define LN_EPS 1e-5f

// ---------------- scratch (device globals; no allocation allowed) -------------
__device__ float g_q[MTOK * CDIM];        // q = x@Wq^T + bq
__device__ float g_query[MTOK * CDIM];    // LN1(q + attn_out)
__device__ float g_h[MTOK * 2 * CDIM];    // gelu(query@W1^T + b1)
__device__ float g_ff[MTOK * CDIM];       // h@W2^T + b2
__device__ float g_uk[BATCH * CDIM];      // pad[b] @ Wk^T
__device__ float g_uv[BATCH * CDIM];      // pad[b] @ Wv^T
__device__ float g_wsk[CDIM];             // row sums of Wk
__device__ float g_wsv[CDIM];             // row sums of Wv

// ---------------- prep: u_k, u_v, wsum_k, wsum_v ------------------------------
// cond[b,s,c] = conv_w[s]*pad[b,c] + conv_b[s];  pad[b,c] = cond_emb[b,(c-2) mod L]
__global__ void prep_kernel(const float* __restrict__ cond_emb,
                            const float* __restrict__ Wk,
                            const float* __restrict__ Wv) {
    __shared__ __align__(16) float s_pad[256];
    int b = blockIdx.x;
    int t = threadIdx.x;
    if (t < 256) {
        int src = (t + 250) % 252;              // (t - 2) mod 252
        s_pad[t] = cond_emb[b * LRAW + src];
    }
    __syncthreads();
    int n = t;                                   // 512 threads, one output chan each
    const float4* wk4 = reinterpret_cast<const float4*>(Wk + (size_t)n * 256);
    const float4* wv4 = reinterpret_cast<const float4*>(Wv + (size_t)n * 256);
    const float4* p4  = reinterpret_cast<const float4*>(s_pad);
    float uk = 0.f, uv = 0.f, sk = 0.f, sv = 0.f;
#pragma unroll 8
    for (int c = 0; c < 64; c++) {
        float4 p = p4[c];
        float4 k = wk4[c];
        float4 v = wv4[c];
        uk += p.x * k.x + p.y * k.y + p.z * k.z + p.w * k.w;
        uv += p.x * v.x + p.y * v.y + p.z * v.z + p.w * v.w;
        sk += k.x + k.y + k.z + k.w;
        sv += v.x + v.y + v.z + v.w;
    }
    g_uk[b * CDIM + n] = uk;
    g_uv[b * CDIM + n] = uv;
    if (b == 0) { g_wsk[n] = sk; g_wsv[n] = sv; }
}

// ---------------- register-tiled SGEMM: C[M,N] = A[M,K] * B[N,K]^T + bias -----
// BM=128, BN=64, BK=16, 256 threads, 8x4 micro-tile. EPI: 0=none, 1=exact GELU.
#define BM 128
#define BN 64
#define BK 16

template <int EPI>
__global__ __launch_bounds__(256)
void sgemm_bias(const float* __restrict__ A, const float* __restrict__ B,
                const float* __restrict__ bias, float* __restrict__ C,
                int M, int N, int K) {
    __shared__ float As[BK][BM];
    __shared__ float Bs[BK][BN];
    const int bm = blockIdx.x * BM;
    const int bn = blockIdx.y * BN;
    const int t  = threadIdx.x;
    const int tx = t & 15;          // 0..15 (cols)
    const int ty = t >> 4;          // 0..15 (rows)

    float acc[8][4] = {};

    for (int k0 = 0; k0 < K; k0 += BK) {
        // load A tile: 128 rows x 16 cols (float4 along K, transpose into As)
#pragma unroll
        for (int j = 0; j < 2; j++) {
            int i   = t + 256 * j;
            int row = i >> 2;
            int kc  = (i & 3) * 4;
            float4 v = *reinterpret_cast<const float4*>(
                &A[(size_t)(bm + row) * K + k0 + kc]);
            As[kc + 0][row] = v.x; As[kc + 1][row] = v.y;
            As[kc + 2][row] = v.z; As[kc + 3][row] = v.w;
        }
        {   // load B tile: 64 rows x 16 cols
            int row = t >> 2;
            int kc  = (t & 3) * 4;
            float4 v = *reinterpret_cast<const float4*>(
                &B[(size_t)(bn + row) * K + k0 + kc]);
            Bs[kc + 0][row] = v.x; Bs[kc + 1][row] = v.y;
            Bs[kc + 2][row] = v.z; Bs[kc + 3][row] = v.w;
        }
        __syncthreads();
#pragma unroll
        for (int k = 0; k < BK; k++) {
            float a[8], b[4];
#pragma unroll
            for (int i = 0; i < 8; i++) a[i] = As[k][ty * 8 + i];
#pragma unroll
            for (int j = 0; j < 4; j++) b[j] = Bs[k][tx * 4 + j];
#pragma unroll
            for (int i = 0; i < 8; i++)
#pragma unroll
                for (int j = 0; j < 4; j++)
                    acc[i][j] = fmaf(a[i], b[j], acc[i][j]);
        }
        __syncthreads();
    }

    const int colb = bn + tx * 4;
    float4 bia = *reinterpret_cast<const float4*>(&bias[colb]);
#pragma unroll
    for (int i = 0; i < 8; i++) {
        int row = bm + ty * 8 + i;
        float4 o;
        o.x = acc[i][0] + bia.x;
        o.y = acc[i][1] + bia.y;
        o.z = acc[i][2] + bia.z;
        o.w = acc[i][3] + bia.w;
        if (EPI == 1) {
            o.x = 0.5f * o.x * (1.0f + erff(o.x * 0.7071067811865475f));
            o.y = 0.5f * o.y * (1.0f + erff(o.y * 0.7071067811865475f));
            o.z = 0.5f * o.z * (1.0f + erff(o.z * 0.7071067811865475f));
            o.w = 0.5f * o.w * (1.0f + erff(o.w * 0.7071067811865475f));
        }
        *reinterpret_cast<float4*>(&C[(size_t)row * N + colb]) = o;
    }
}

// ---------------- attention (collapsed) + LN1: one warp per token -------------
__global__ __launch_bounds__(256)
void attn_ln1_kernel(const float* __restrict__ bv,
                     const float* __restrict__ conv_w,
                     const float* __restrict__ conv_b,
                     const float* __restrict__ ln1_w,
                     const float* __restrict__ ln1_b) {
    __shared__ __align__(16) float s_uk[CDIM], s_uv[CDIM], s_wsk[CDIM],
                                   s_wsv[CDIM], s_bv[CDIM], s_lw[CDIM],
                                   s_lb[CDIM], s_cw[SLEN], s_cb[SLEN];
    const int t = threadIdx.x;
    const int token0 = blockIdx.x * 8;
    const int b = token0 >> 10;                 // T = 1024 tokens per batch
    for (int i = t; i < CDIM; i += 256) {
        s_uk[i] = g_uk[b * CDIM + i];
        s_uv[i] = g_uv[b * CDIM + i];
        s_wsk[i] = g_wsk[i];
        s_wsv[i] = g_wsv[i];
        s_bv[i] = bv[i];
        s_lw[i] = ln1_w[i];
        s_lb[i] = ln1_b[i];
    }
    if (t < SLEN) { s_cw[t] = conv_w[t]; s_cb[t] = conv_b[t]; }
    __syncthreads();

    const int warp = t >> 5, lane = t & 31;
    const int token = token0 + warp;
    const float4* qrow = reinterpret_cast<const float4*>(g_q + (size_t)token * CDIM);

    float4 qv[4];
    float A = 0.f, Bk = 0.f;
#pragma unroll
    for (int j = 0; j < 4; j++) {
        int i4 = j * 32 + lane;
        qv[j] = qrow[i4];
        float4 uk = reinterpret_cast<const float4*>(s_uk)[i4];
        float4 wk = reinterpret_cast<const float4*>(s_wsk)[i4];
        A  += qv[j].x * uk.x + qv[j].y * uk.y + qv[j].z * uk.z + qv[j].w * uk.w;
        Bk += qv[j].x * wk.x + qv[j].y * wk.y + qv[j].z * wk.z + qv[j].w * wk.w;
    }
#pragma unroll
    for (int o = 16; o > 0; o >>= 1) {
        A  += __shfl_xor_sync(0xffffffffu, A, o);
        Bk += __shfl_xor_sync(0xffffffffu, Bk, o);
    }

    const float scale = 0.04419417382415922f;   // 1/sqrt(512)
    float l[4], m = -1e30f;
#pragma unroll
    for (int j = 0; j < 4; j++) {
        int s = j * 32 + lane;
        l[j] = scale * (s_cw[s] * A + s_cb[s] * Bk);
        m = fmaxf(m, l[j]);
    }
#pragma unroll
    for (int o = 16; o > 0; o >>= 1)
        m = fmaxf(m, __shfl_xor_sync(0xffffffffu, m, o));

    float Z = 0.f, an = 0.f, bn = 0.f;
#pragma unroll
    for (int j = 0; j < 4; j++) {
        int s = j * 32 + lane;
        float e = expf(l[j] - m);
        Z += e;
        an += e * s_cw[s];
        bn += e * s_cb[s];
    }
#pragma unroll
    for (int o = 16; o > 0; o >>= 1) {
        Z  += __shfl_xor_sync(0xffffffffu, Z, o);
        an += __shfl_xor_sync(0xffffffffu, an, o);
        bn += __shfl_xor_sync(0xffffffffu, bn, o);
    }
    const float alpha = an / Z;
    const float beta  = bn / Z;

    // y = q + attn_out;  LN1
    float y[16];
    float sum = 0.f, sq = 0.f;
#pragma unroll
    for (int j = 0; j < 4; j++) {
        int i4 = j * 32 + lane;
        float4 uv = reinterpret_cast<const float4*>(s_uv)[i4];
        float4 wv = reinterpret_cast<const float4*>(s_wsv)[i4];
        float4 bb = reinterpret_cast<const float4*>(s_bv)[i4];
        float y0 = qv[j].x + alpha * uv.x + beta * wv.x + bb.x;
        float y1 = qv[j].y + alpha * uv.y + beta * wv.y + bb.y;
        float y2 = qv[j].z + alpha * uv.z + beta * wv.z + bb.z;
        float y3 = qv[j].w + alpha * uv.w + beta * wv.w + bb.w;
        y[j * 4 + 0] = y0; y[j * 4 + 1] = y1; y[j * 4 + 2] = y2; y[j * 4 + 3] = y3;
        sum += y0 + y1 + y2 + y3;
        sq  += y0 * y0 + y1 * y1 + y2 * y2 + y3 * y3;
    }
#pragma unroll
    for (int o = 16; o > 0; o >>= 1) {
        sum += __shfl_xor_sync(0xffffffffu, sum, o);
        sq  += __shfl_xor_sync(0xffffffffu, sq, o);
    }
    const float mean = sum * (1.f / 512.f);
    const float var  = sq * (1.f / 512.f) - mean * mean;
    const float rstd = rsqrtf(var + LN_EPS);

    float4* orow = reinterpret_cast<float4*>(g_query + (size_t)token * CDIM);
#pragma unroll
    for (int j = 0; j < 4; j++) {
        int i4 = j * 32 + lane;
        float4 lw = reinterpret_cast<const float4*>(s_lw)[i4];
        float4 lb = reinterpret_cast<const float4*>(s_lb)[i4];
        float4 o;
        o.x = (y[j * 4 + 0] - mean) * rstd * lw.x + lb.x;
        o.y = (y[j * 4 + 1] - mean) * rstd * lw.y + lb.y;
        o.z = (y[j * 4 + 2] - mean) * rstd * lw.z + lb.z;
        o.w = (y[j * 4 + 3] - mean) * rstd * lw.w + lb.w;
        orow[i4] = o;
    }
}

// ---------------- LN2(query + ff) + x: one warp per token ---------------------
__global__ __launch_bounds__(256)
void ln2_add_kernel(const float* __restrict__ x,
                    const float* __restrict__ ln2_w,
                    const float* __restrict__ ln2_b,
                    float* __restrict__ out) {
    const int t = threadIdx.x;
    const int warp = t >> 5, lane = t & 31;
    const int token = blockIdx.x * 8 + warp;
    const float4* qr = reinterpret_cast<const float4*>(g_query + (size_t)token * CDIM);
    const float4* fr = reinterpret_cast<const float4*>(g_ff + (size_t)token * CDIM);
    const float4* xr = reinterpret_cast<const float4*>(x + (size_t)token * CDIM);
    float4* orow = reinterpret_cast<float4*>(out + (size_t)token * CDIM);

    float y[16];
    float4 xs[4];
    float sum = 0.f, sq = 0.f;
#pragma unroll
    for (int j = 0; j < 4; j++) {
        int i4 = j * 32 + lane;
        float4 a = qr[i4];
        float4 f = fr[i4];
        xs[j] = xr[i4];
        float y0 = a.x + f.x, y1 = a.y + f.y, y2 = a.z + f.z, y3 = a.w + f.w;
        y[j * 4 + 0] = y0; y[j * 4 + 1] = y1; y[j * 4 + 2] = y2; y[j * 4 + 3] = y3;
        sum += y0 + y1 + y2 + y3;
        sq  += y0 * y0 + y1 * y1 + y2 * y2 + y3 * y3;
    }
#pragma unroll
    for (int o = 16; o > 0; o >>= 1) {
        sum += __shfl_xor_sync(0xffffffffu, sum, o);
        sq  += __shfl_xor_sync(0xffffffffu, sq, o);
    }
    const float mean = sum * (1.f / 512.f);
    const float var  = sq * (1.f / 512.f) - mean * mean;
    const float rstd = rsqrtf(var + LN_EPS);

#pragma unroll
    for (int j = 0; j < 4; j++) {
        int i4 = j * 32 + lane;
        float4 lw = reinterpret_cast<const float4*>(ln2_w)[i4];
        float4 lb = reinterpret_cast<const float4*>(ln2_b)[i4];
        float4 o;
        o.x = (y[j * 4 + 0] - mean) * rstd * lw.x + lb.x + xs[j].x;
        o.y = (y[j * 4 + 1] - mean) * rstd * lw.y + lb.y + xs[j].y;
        o.z = (y[j * 4 + 2] - mean) * rstd * lw.z + lb.z + xs[j].z;
        o.w = (y[j * 4 + 3] - mean) * rstd * lw.w + lb.w + xs[j].w;
        orow[i4] = o;
    }
}

// ---------------- launch ------------------------------------------------------
extern "C" void kernel_launch(void* const* d_in, const int* in_sizes, int n_in,
                              void* d_out, int out_size) {
    const float* x        = (const float*)d_in[0];
    const float* cond_emb = (const float*)d_in[1];
    const float* Wq       = (const float*)d_in[2];
    const float* bq       = (const float*)d_in[3];
    const float* Wk       = (const float*)d_in[4];
    // const float* bk    = (const float*)d_in[5];  // constant shift, cancels in softmax
    const float* Wv       = (const float*)d_in[6];
    const float* bv       = (const float*)d_in[7];
    const float* conv_w   = (const float*)d_in[8];
    const float* conv_b   = (const float*)d_in[9];
    const float* ln1_w    = (const float*)d_in[10];
    const float* ln1_b    = (const float*)d_in[11];
    const float* W1       = (const float*)d_in[12];
    const float* b1       = (const float*)d_in[13];
    const float* W2       = (const float*)d_in[14];
    const float* b2       = (const float*)d_in[15];
    const float* ln2_w    = (const float*)d_in[16];
    const float* ln2_b    = (const float*)d_in[17];
    float* out            = (float*)d_out;

    float *pq, *pquery, *ph, *pff;
    cudaGetSymbolAddress((void**)&pq, g_q);
    cudaGetSymbolAddress((void**)&pquery, g_query);
    cudaGetSymbolAddress((void**)&ph, g_h);
    cudaGetSymbolAddress((void**)&pff, g_ff);

    // 1) conditioner factorization
    prep_kernel<<<BATCH, 512>>>(cond_emb, Wk, Wv);

    // 2) q = x @ Wq^T + bq           [32768,512] x [512,512]
    sgemm_bias<0><<<dim3(MTOK / BM, CDIM / BN), 256>>>(x, Wq, bq, pq,
                                                       MTOK, CDIM, CDIM);

    // 3) collapsed attention + LN1 -> query
    attn_ln1_kernel<<<MTOK / 8, 256>>>(bv, conv_w, conv_b, ln1_w, ln1_b);

    // 4) h = gelu(query @ W1^T + b1) [32768,1024] x [1024,512]
    sgemm_bias<1><<<dim3(MTOK / BM, (2 * CDIM) / BN), 256>>>(pquery, W1, b1, ph,
                                                             MTOK, 2 * CDIM, CDIM);

    // 5) ff = h @ W2^T + b2          [32768,512] x [512,1024]
    sgemm_bias<0><<<dim3(MTOK / BM, CDIM / BN), 256>>>(ph, W2, b2, pff,
                                                       MTOK, CDIM, 2 * CDIM);

    // 6) out = LN2(query + ff) + x
    ln2_add_kernel<<<MTOK / 8, 256>>>(x, ln2_w, ln2_b, out);
}

// round 5
// speedup vs baseline: 1.0218x; 1.0218x over previous
#include <cuda_runtime.h>
#include <cuda_bf16.h>
#include <math.h>
#include <stdint.h>

// Problem constants
#define BATCH 32
#define SEQT  1024
#define CDIM  512
#define LRAW  252
#define SLEN  128
#define MTOK  (BATCH * SEQT)   // 32768
#define LN_EPS 1e-5f

// ---------------- scratch (device globals; no allocation allowed) -------------
__device__ float g_q[MTOK * CDIM];        // q = x@Wq^T + bq
__device__ float g_query[MTOK * CDIM];    // LN1(q + attn_out)
__device__ float g_h[MTOK * 2 * CDIM];    // gelu(query@W1^T + b1)
__device__ float g_ff[MTOK * CDIM];       // h@W2^T + b2
__device__ float g_uk[BATCH * CDIM];      // pad[b] @ Wk^T
__device__ float g_uv[BATCH * CDIM];      // pad[b] @ Wv^T
__device__ float g_wsk[CDIM];             // row sums of Wk
__device__ float g_wsv[CDIM];             // row sums of Wv

// =============================================================================
// helpers
// =============================================================================
__device__ __forceinline__ uint32_t smem_u32(const void* p) {
    uint32_t a;
    asm("{ .reg .u64 t; cvta.to.shared.u64 t, %1; cvt.u32.u64 %0, t; }"
        : "=r"(a) : "l"(p));
    return a;
}

// split fp32 pair into packed bf16 hi / lo words
__device__ __forceinline__ void split2(float a, float b, uint32_t& hi, uint32_t& lo) {
    __nv_bfloat16 ha = __float2bfloat16(a), hb = __float2bfloat16(b);
    __nv_bfloat16 la = __float2bfloat16(a - __bfloat162float(ha));
    __nv_bfloat16 lb = __float2bfloat16(b - __bfloat162float(hb));
    hi = (uint32_t)__bfloat16_as_ushort(ha) | ((uint32_t)__bfloat16_as_ushort(hb) << 16);
    lo = (uint32_t)__bfloat16_as_ushort(la) | ((uint32_t)__bfloat16_as_ushort(lb) << 16);
}

__device__ __forceinline__ void ldsm4(uint32_t& r0, uint32_t& r1, uint32_t& r2,
                                      uint32_t& r3, uint32_t addr) {
    asm volatile("ldmatrix.sync.aligned.m8n8.x4.shared.b16 {%0,%1,%2,%3}, [%4];"
                 : "=r"(r0), "=r"(r1), "=r"(r2), "=r"(r3) : "r"(addr));
}

__device__ __forceinline__ void mma16816(float* d, const uint32_t* a,
                                         const uint32_t* b) {
    asm volatile(
        "mma.sync.aligned.m16n8k16.row.col.f32.bf16.bf16.f32 "
        "{%0,%1,%2,%3}, {%4,%5,%6,%7}, {%8,%9}, {%0,%1,%2,%3};"
        : "+f"(d[0]), "+f"(d[1]), "+f"(d[2]), "+f"(d[3])
        : "r"(a[0]), "r"(a[1]), "r"(a[2]), "r"(a[3]), "r"(b[0]), "r"(b[1]));
}

// =============================================================================
// Tensor-core split-bf16 GEMM (mma.sync): C[M,N] = A[M,K] * B[N,K]^T + bias
// CTA tile 128x128, K-chunk 64 (bf16 rows = 128B, XOR-swizzled), double-buffered
// SMEM (2 x 64KB), 256 threads = 8 warps, warp tile 64x32 (4x4 m16n8k16).
// D += Ahi*Bhi + Ahi*Blo + Alo*Bhi  (lo*lo dropped, ~2^-18)
// EPI: 0=none, 1=exact GELU.
// =============================================================================
#define STAGE_BYTES 65536   // Ahi 16K | Alo 16K | Bhi 16K | Blo 16K
#define GT_SMEM (2 * STAGE_BYTES)

template <int EPI>
__global__ void __launch_bounds__(256, 1)
gemm_mma(const float* __restrict__ A, const float* __restrict__ B,
         const float* __restrict__ bias, float* __restrict__ C,
         int N, int K) {
    extern __shared__ __align__(1024) char sm[];
    const int tid = threadIdx.x;
    const int wid = tid >> 5, lane = tid & 31;
    const int bn = blockIdx.x * 128;     // x = N tile (A reuse across wave via L2)
    const int bm = blockIdx.y * 128;

    // ---- loader mapping: 2 threads per row, 32 fp32 each ----
    const int lr = tid >> 1;             // 0..127
    const int lc = (tid & 1) * 32;       // fp32 column block within 64-chunk
    const float4* Ald = reinterpret_cast<const float4*>(A + (size_t)(bm + lr) * K + lc);
    const float4* Bld = reinterpret_cast<const float4*>(B + (size_t)(bn + lr) * K + lc);
    const int rowstride4 = K >> 2;       // float4 per row (unused; base ptr holds row)
    (void)rowstride4;
    const uint32_t xw = (uint32_t)(lr & 7) << 4;   // store-side swizzle

    const int nc = K >> 6;               // chunks of 64

    float4 ra[8], rb[8];
    auto LOAD = [&](int c) {
        const float4* pa = Ald + c * 16;
        const float4* pb = Bld + c * 16;
#pragma unroll
        for (int f = 0; f < 8; ++f) { ra[f] = pa[f]; rb[f] = pb[f]; }
    };
    auto STORE = [&](int s) {
        char* base = sm + s * STAGE_BYTES;
#pragma unroll
        for (int f = 0; f < 8; ++f) {
            uint32_t off = (uint32_t)lr * 128 + ((((uint32_t)lc + f * 4) * 2) ^ xw);
            uint2 h, l;
            split2(ra[f].x, ra[f].y, h.x, l.x);
            split2(ra[f].z, ra[f].w, h.y, l.y);
            *reinterpret_cast<uint2*>(base + off)         = h;
            *reinterpret_cast<uint2*>(base + 16384 + off) = l;
            split2(rb[f].x, rb[f].y, h.x, l.x);
            split2(rb[f].z, rb[f].w, h.y, l.y);
            *reinterpret_cast<uint2*>(base + 32768 + off) = h;
            *reinterpret_cast<uint2*>(base + 49152 + off) = l;
        }
    };

    // ---- mma-side addressing ----
    const int wm = wid & 1, wn = wid >> 1;          // 2 x 4 warps
    const uint32_t smb = smem_u32(sm);
    const uint32_t xorm = (uint32_t)(lane & 7) << 4;
    const uint32_t rowA = (uint32_t)(wm * 64 + ((lane >> 3) & 1) * 8 + (lane & 7));
    const uint32_t kaddA = (uint32_t)(((lane >> 4) & 1) * 16);
    const uint32_t rowB = (uint32_t)(wn * 32 + ((lane >> 4) & 1) * 8 + (lane & 7));
    const uint32_t kaddB = (uint32_t)(((lane >> 3) & 1) * 16);

    float acc[4][4][4];
#pragma unroll
    for (int i = 0; i < 4; ++i)
#pragma unroll
        for (int j = 0; j < 4; ++j)
#pragma unroll
            for (int e = 0; e < 4; ++e) acc[i][j][e] = 0.f;

    auto MMA_CHUNK = [&](int s) {
        const uint32_t aHi = smb + s * STAGE_BYTES;
        const uint32_t aLo = aHi + 16384;
        const uint32_t bHi = aHi + 32768;
        const uint32_t bLo = aHi + 49152;
#pragma unroll
        for (int ks = 0; ks < 4; ++ks) {
            const uint32_t kb = ks * 32;
            uint32_t ah[4][4], al[4][4], bh[4][2], bl[4][2];
#pragma unroll
            for (int i = 0; i < 4; ++i) {
                uint32_t off = (rowA + i * 16) * 128 + ((kb + kaddA) ^ xorm);
                ldsm4(ah[i][0], ah[i][1], ah[i][2], ah[i][3], aHi + off);
                ldsm4(al[i][0], al[i][1], al[i][2], al[i][3], aLo + off);
            }
#pragma unroll
            for (int j2 = 0; j2 < 2; ++j2) {
                uint32_t off = (rowB + j2 * 16) * 128 + ((kb + kaddB) ^ xorm);
                ldsm4(bh[2 * j2][0], bh[2 * j2][1], bh[2 * j2 + 1][0],
                      bh[2 * j2 + 1][1], bHi + off);
                ldsm4(bl[2 * j2][0], bl[2 * j2][1], bl[2 * j2 + 1][0],
                      bl[2 * j2 + 1][1], bLo + off);
            }
#pragma unroll
            for (int i = 0; i < 4; ++i)
#pragma unroll
                for (int j = 0; j < 4; ++j) {
                    mma16816(acc[i][j], ah[i], bh[j]);
                    mma16816(acc[i][j], ah[i], bl[j]);
                    mma16816(acc[i][j], al[i], bh[j]);
                }
        }
    };

    // ---- pipelined main loop ----
    LOAD(0);
    STORE(0);
    __syncthreads();
    for (int c = 0; c < nc; ++c) {
        if (c + 1 < nc) LOAD(c + 1);
        MMA_CHUNK(c & 1);
        __syncthreads();
        if (c + 1 < nc) {
            STORE((c + 1) & 1);
            __syncthreads();
        }
    }

    // ---- epilogue ----
#pragma unroll
    for (int i = 0; i < 4; ++i) {
        const int r0 = bm + wm * 64 + i * 16 + (lane >> 2);
#pragma unroll
        for (int j = 0; j < 4; ++j) {
            const int cc = bn + wn * 32 + j * 8 + (lane & 3) * 2;
            float2 bi = *reinterpret_cast<const float2*>(bias + cc);
            float o0 = acc[i][j][0] + bi.x, o1 = acc[i][j][1] + bi.y;
            float o2 = acc[i][j][2] + bi.x, o3 = acc[i][j][3] + bi.y;
            if (EPI == 1) {
                o0 = 0.5f * o0 * (1.0f + erff(o0 * 0.7071067811865475f));
                o1 = 0.5f * o1 * (1.0f + erff(o1 * 0.7071067811865475f));
                o2 = 0.5f * o2 * (1.0f + erff(o2 * 0.7071067811865475f));
                o3 = 0.5f * o3 * (1.0f + erff(o3 * 0.7071067811865475f));
            }
            *reinterpret_cast<float2*>(C + (size_t)r0 * N + cc) = make_float2(o0, o1);
            *reinterpret_cast<float2*>(C + (size_t)(r0 + 8) * N + cc) = make_float2(o2, o3);
        }
    }
}

// ---------------- prep: u_k, u_v, wsum_k, wsum_v ------------------------------
__global__ void prep_kernel(const float* __restrict__ cond_emb,
                            const float* __restrict__ Wk,
                            const float* __restrict__ Wv) {
    __shared__ __align__(16) float s_pad[256];
    int b = blockIdx.x;
    int t = threadIdx.x;
    if (t < 256) {
        int src = (t + 250) % 252;              // (t - 2) mod 252
        s_pad[t] = cond_emb[b * LRAW + src];
    }
    __syncthreads();
    int n = t;
    const float4* wk4 = reinterpret_cast<const float4*>(Wk + (size_t)n * 256);
    const float4* wv4 = reinterpret_cast<const float4*>(Wv + (size_t)n * 256);
    const float4* p4  = reinterpret_cast<const float4*>(s_pad);
    float uk = 0.f, uv = 0.f, sk = 0.f, sv = 0.f;
#pragma unroll 8
    for (int c = 0; c < 64; c++) {
        float4 p = p4[c];
        float4 k = wk4[c];
        float4 v = wv4[c];
        uk += p.x * k.x + p.y * k.y + p.z * k.z + p.w * k.w;
        uv += p.x * v.x + p.y * v.y + p.z * v.z + p.w * v.w;
        sk += k.x + k.y + k.z + k.w;
        sv += v.x + v.y + v.z + v.w;
    }
    g_uk[b * CDIM + n] = uk;
    g_uv[b * CDIM + n] = uv;
    if (b == 0) { g_wsk[n] = sk; g_wsv[n] = sv; }
}

// ---------------- attention (collapsed) + LN1: one warp per token -------------
__global__ __launch_bounds__(256)
void attn_ln1_kernel(const float* __restrict__ bv,
                     const float* __restrict__ conv_w,
                     const float* __restrict__ conv_b,
                     const float* __restrict__ ln1_w,
                     const float* __restrict__ ln1_b) {
    __shared__ __align__(16) float s_uk[CDIM], s_uv[CDIM], s_wsk[CDIM],
                                   s_wsv[CDIM], s_bv[CDIM], s_lw[CDIM],
                                   s_lb[CDIM], s_cw[SLEN], s_cb[SLEN];
    const int t = threadIdx.x;
    const int token0 = blockIdx.x * 8;
    const int b = token0 >> 10;
    for (int i = t; i < CDIM; i += 256) {
        s_uk[i] = g_uk[b * CDIM + i];
        s_uv[i] = g_uv[b * CDIM + i];
        s_wsk[i] = g_wsk[i];
        s_wsv[i] = g_wsv[i];
        s_bv[i] = bv[i];
        s_lw[i] = ln1_w[i];
        s_lb[i] = ln1_b[i];
    }
    if (t < SLEN) { s_cw[t] = conv_w[t]; s_cb[t] = conv_b[t]; }
    __syncthreads();

    const int warp = t >> 5, lane = t & 31;
    const int token = token0 + warp;
    const float4* qrow = reinterpret_cast<const float4*>(g_q + (size_t)token * CDIM);

    float4 qv[4];
    float A = 0.f, Bk = 0.f;
#pragma unroll
    for (int j = 0; j < 4; j++) {
        int i4 = j * 32 + lane;
        qv[j] = qrow[i4];
        float4 uk = reinterpret_cast<const float4*>(s_uk)[i4];
        float4 wk = reinterpret_cast<const float4*>(s_wsk)[i4];
        A  += qv[j].x * uk.x + qv[j].y * uk.y + qv[j].z * uk.z + qv[j].w * uk.w;
        Bk += qv[j].x * wk.x + qv[j].y * wk.y + qv[j].z * wk.z + qv[j].w * wk.w;
    }
#pragma unroll
    for (int o = 16; o > 0; o >>= 1) {
        A  += __shfl_xor_sync(0xffffffffu, A, o);
        Bk += __shfl_xor_sync(0xffffffffu, Bk, o);
    }

    const float scale = 0.04419417382415922f;   // 1/sqrt(512)
    float l[4], m = -1e30f;
#pragma unroll
    for (int j = 0; j < 4; j++) {
        int s = j * 32 + lane;
        l[j] = scale * (s_cw[s] * A + s_cb[s] * Bk);
        m = fmaxf(m, l[j]);
    }
#pragma unroll
    for (int o = 16; o > 0; o >>= 1)
        m = fmaxf(m, __shfl_xor_sync(0xffffffffu, m, o));

    float Z = 0.f, an = 0.f, bn = 0.f;
#pragma unroll
    for (int j = 0; j < 4; j++) {
        int s = j * 32 + lane;
        float e = expf(l[j] - m);
        Z += e;
        an += e * s_cw[s];
        bn += e * s_cb[s];
    }
#pragma unroll
    for (int o = 16; o > 0; o >>= 1) {
        Z  += __shfl_xor_sync(0xffffffffu, Z, o);
        an += __shfl_xor_sync(0xffffffffu, an, o);
        bn += __shfl_xor_sync(0xffffffffu, bn, o);
    }
    const float alpha = an / Z;
    const float beta  = bn / Z;

    float y[16];
    float sum = 0.f, sq = 0.f;
#pragma unroll
    for (int j = 0; j < 4; j++) {
        int i4 = j * 32 + lane;
        float4 uv = reinterpret_cast<const float4*>(s_uv)[i4];
        float4 wv = reinterpret_cast<const float4*>(s_wsv)[i4];
        float4 bb = reinterpret_cast<const float4*>(s_bv)[i4];
        float y0 = qv[j].x + alpha * uv.x + beta * wv.x + bb.x;
        float y1 = qv[j].y + alpha * uv.y + beta * wv.y + bb.y;
        float y2 = qv[j].z + alpha * uv.z + beta * wv.z + bb.z;
        float y3 = qv[j].w + alpha * uv.w + beta * wv.w + bb.w;
        y[j * 4 + 0] = y0; y[j * 4 + 1] = y1; y[j * 4 + 2] = y2; y[j * 4 + 3] = y3;
        sum += y0 + y1 + y2 + y3;
        sq  += y0 * y0 + y1 * y1 + y2 * y2 + y3 * y3;
    }
#pragma unroll
    for (int o = 16; o > 0; o >>= 1) {
        sum += __shfl_xor_sync(0xffffffffu, sum, o);
        sq  += __shfl_xor_sync(0xffffffffu, sq, o);
    }
    const float mean = sum * (1.f / 512.f);
    const float var  = sq * (1.f / 512.f) - mean * mean;
    const float rstd = rsqrtf(var + LN_EPS);

    float4* orow = reinterpret_cast<float4*>(g_query + (size_t)token * CDIM);
#pragma unroll
    for (int j = 0; j < 4; j++) {
        int i4 = j * 32 + lane;
        float4 lw = reinterpret_cast<const float4*>(s_lw)[i4];
        float4 lb = reinterpret_cast<const float4*>(s_lb)[i4];
        float4 o;
        o.x = (y[j * 4 + 0] - mean) * rstd * lw.x + lb.x;
        o.y = (y[j * 4 + 1] - mean) * rstd * lw.y + lb.y;
        o.z = (y[j * 4 + 2] - mean) * rstd * lw.z + lb.z;
        o.w = (y[j * 4 + 3] - mean) * rstd * lw.w + lb.w;
        orow[i4] = o;
    }
}

// ---------------- LN2(query + ff) + x: one warp per token ---------------------
__global__ __launch_bounds__(256)
void ln2_add_kernel(const float* __restrict__ x,
                    const float* __restrict__ ln2_w,
                    const float* __restrict__ ln2_b,
                    float* __restrict__ out) {
    const int t = threadIdx.x;
    const int warp = t >> 5, lane = t & 31;
    const int token = blockIdx.x * 8 + warp;
    const float4* qr = reinterpret_cast<const float4*>(g_query + (size_t)token * CDIM);
    const float4* fr = reinterpret_cast<const float4*>(g_ff + (size_t)token * CDIM);
    const float4* xr = reinterpret_cast<const float4*>(x + (size_t)token * CDIM);
    float4* orow = reinterpret_cast<float4*>(out + (size_t)token * CDIM);

    float y[16];
    float4 xs[4];
    float sum = 0.f, sq = 0.f;
#pragma unroll
    for (int j = 0; j < 4; j++) {
        int i4 = j * 32 + lane;
        float4 a = qr[i4];
        float4 f = fr[i4];
        xs[j] = xr[i4];
        float y0 = a.x + f.x, y1 = a.y + f.y, y2 = a.z + f.z, y3 = a.w + f.w;
        y[j * 4 + 0] = y0; y[j * 4 + 1] = y1; y[j * 4 + 2] = y2; y[j * 4 + 3] = y3;
        sum += y0 + y1 + y2 + y3;
        sq  += y0 * y0 + y1 * y1 + y2 * y2 + y3 * y3;
    }
#pragma unroll
    for (int o = 16; o > 0; o >>= 1) {
        sum += __shfl_xor_sync(0xffffffffu, sum, o);
        sq  += __shfl_xor_sync(0xffffffffu, sq, o);
    }
    const float mean = sum * (1.f / 512.f);
    const float var  = sq * (1.f / 512.f) - mean * mean;
    const float rstd = rsqrtf(var + LN_EPS);

#pragma unroll
    for (int j = 0; j < 4; j++) {
        int i4 = j * 32 + lane;
        float4 lw = reinterpret_cast<const float4*>(ln2_w)[i4];
        float4 lb = reinterpret_cast<const float4*>(ln2_b)[i4];
        float4 o;
        o.x = (y[j * 4 + 0] - mean) * rstd * lw.x + lb.x + xs[j].x;
        o.y = (y[j * 4 + 1] - mean) * rstd * lw.y + lb.y + xs[j].y;
        o.z = (y[j * 4 + 2] - mean) * rstd * lw.z + lb.z + xs[j].z;
        o.w = (y[j * 4 + 3] - mean) * rstd * lw.w + lb.w + xs[j].w;
        orow[i4] = o;
    }
}

// ---------------- launch ------------------------------------------------------
extern "C" void kernel_launch(void* const* d_in, const int* in_sizes, int n_in,
                              void* d_out, int out_size) {
    const float* x        = (const float*)d_in[0];
    const float* cond_emb = (const float*)d_in[1];
    const float* Wq       = (const float*)d_in[2];
    const float* bq       = (const float*)d_in[3];
    const float* Wk       = (const float*)d_in[4];
    // d_in[5] = bk: constant shift along s, cancels in softmax
    const float* Wv       = (const float*)d_in[6];
    const float* bv       = (const float*)d_in[7];
    const float* conv_w   = (const float*)d_in[8];
    const float* conv_b   = (const float*)d_in[9];
    const float* ln1_w    = (const float*)d_in[10];
    const float* ln1_b    = (const float*)d_in[11];
    const float* W1       = (const float*)d_in[12];
    const float* b1       = (const float*)d_in[13];
    const float* W2       = (const float*)d_in[14];
    const float* b2       = (const float*)d_in[15];
    const float* ln2_w    = (const float*)d_in[16];
    const float* ln2_b    = (const float*)d_in[17];
    float* out            = (float*)d_out;

    float *pq, *pquery, *ph, *pff;
    cudaGetSymbolAddress((void**)&pq, g_q);
    cudaGetSymbolAddress((void**)&pquery, g_query);
    cudaGetSymbolAddress((void**)&ph, g_h);
    cudaGetSymbolAddress((void**)&pff, g_ff);

    cudaFuncSetAttribute(gemm_mma<0>, cudaFuncAttributeMaxDynamicSharedMemorySize,
                         GT_SMEM);
    cudaFuncSetAttribute(gemm_mma<1>, cudaFuncAttributeMaxDynamicSharedMemorySize,
                         GT_SMEM);

    // 1) conditioner factorization
    prep_kernel<<<BATCH, 512>>>(cond_emb, Wk, Wv);

    // 2) q = x @ Wq^T + bq           [32768,512] x [512,512]
    gemm_mma<0><<<dim3(CDIM / 128, MTOK / 128), 256, GT_SMEM>>>(
        x, Wq, bq, pq, CDIM, CDIM);

    // 3) collapsed attention + LN1 -> query
    attn_ln1_kernel<<<MTOK / 8, 256>>>(bv, conv_w, conv_b, ln1_w, ln1_b);

    // 4) h = gelu(query @ W1^T + b1) [32768,1024] x [1024,512]
    gemm_mma<1><<<dim3((2 * CDIM) / 128, MTOK / 128), 256, GT_SMEM>>>(
        pquery, W1, b1, ph, 2 * CDIM, CDIM);

    // 5) ff = h @ W2^T + b2          [32768,512] x [512,1024]
    gemm_mma<0><<<dim3(CDIM / 128, MTOK / 128), 256, GT_SMEM>>>(
        ph, W2, b2, pff, CDIM, 2 * CDIM);

    // 6) out = LN2(query + ff) + x
    ln2_add_kernel<<<MTOK / 8, 256>>>(x, ln2_w, ln2_b, out);
}

// round 7
// speedup vs baseline: 2.7120x; 2.6542x over previous
#include <cuda_runtime.h>
#include <cuda_bf16.h>
#include <math.h>
#include <stdint.h>

// Problem constants
#define BATCH 32
#define SEQT  1024
#define CDIM  512
#define LRAW  252
#define SLEN  128
#define MTOK  (BATCH * SEQT)   // 32768
#define LN_EPS 1e-5f

// ---------------- scratch (device globals; no allocation allowed) -------------
__device__ float g_q[MTOK * CDIM];            // q = x@Wq^T + bq
__device__ float g_query[MTOK * CDIM];        // LN1(q + attn_out) fp32 (for residual)
__device__ float g_ff[MTOK * CDIM];           // h@W2^T + b2
__device__ float g_uk[BATCH * CDIM];
__device__ float g_uv[BATCH * CDIM];
__device__ float g_wsk[CDIM];
__device__ float g_wsv[CDIM];

// bf16 hi/lo split operands
__device__ __nv_bfloat16 g_xhi[MTOK * CDIM],      g_xlo[MTOK * CDIM];
__device__ __nv_bfloat16 g_qyhi[MTOK * CDIM],     g_qylo[MTOK * CDIM];     // query
__device__ __nv_bfloat16 g_hhi[MTOK * 2 * CDIM],  g_hlo[MTOK * 2 * CDIM];  // gelu out
__device__ __nv_bfloat16 g_wqhi[CDIM * CDIM],     g_wqlo[CDIM * CDIM];
__device__ __nv_bfloat16 g_w1hi[2 * CDIM * CDIM], g_w1lo[2 * CDIM * CDIM];
__device__ __nv_bfloat16 g_w2hi[CDIM * 2 * CDIM], g_w2lo[CDIM * 2 * CDIM];

// =============================================================================
// helpers
// =============================================================================
__device__ __forceinline__ uint32_t smem_u32(const void* p) {
    uint32_t a;
    asm("{ .reg .u64 t; cvta.to.shared.u64 t, %1; cvt.u32.u64 %0, t; }"
        : "=r"(a) : "l"(p));
    return a;
}

__device__ __forceinline__ void split2(float a, float b, uint32_t& hi, uint32_t& lo) {
    __nv_bfloat16 ha = __float2bfloat16(a), hb = __float2bfloat16(b);
    __nv_bfloat16 la = __float2bfloat16(a - __bfloat162float(ha));
    __nv_bfloat16 lb = __float2bfloat16(b - __bfloat162float(hb));
    hi = (uint32_t)__bfloat16_as_ushort(ha) | ((uint32_t)__bfloat16_as_ushort(hb) << 16);
    lo = (uint32_t)__bfloat16_as_ushort(la) | ((uint32_t)__bfloat16_as_ushort(lb) << 16);
}

__device__ __forceinline__ void ldsm4(uint32_t& r0, uint32_t& r1, uint32_t& r2,
                                      uint32_t& r3, uint32_t addr) {
    asm volatile("ldmatrix.sync.aligned.m8n8.x4.shared.b16 {%0,%1,%2,%3}, [%4];"
                 : "=r"(r0), "=r"(r1), "=r"(r2), "=r"(r3) : "r"(addr));
}

__device__ __forceinline__ void mma16816(float* d, const uint32_t* a,
                                         const uint32_t* b) {
    asm volatile(
        "mma.sync.aligned.m16n8k16.row.col.f32.bf16.bf16.f32 "
        "{%0,%1,%2,%3}, {%4,%5,%6,%7}, {%8,%9}, {%0,%1,%2,%3};"
        : "+f"(d[0]), "+f"(d[1]), "+f"(d[2]), "+f"(d[3])
        : "r"(a[0]), "r"(a[1]), "r"(a[2]), "r"(a[3]), "r"(b[0]), "r"(b[1]));
}

__device__ __forceinline__ void cp16(uint32_t dst, const void* src) {
    asm volatile("cp.async.cg.shared.global [%0], [%1], 16;"
                 :: "r"(dst), "l"(src));
}

// =============================================================================
// Pipelined split-bf16 GEMM (mma.sync): C[M,N] = A[M,K] * B[N,K]^T + bias
// Operands pre-split in global (hi/lo bf16). CTA 128x128, K-chunk 64 (128B rows,
// XOR swizzle), cp.async 3-stage, 512 threads = 16 warps (4x4), warp tile 32x32.
// D += Ahi*Bhi + Ahi*Blo + Alo*Bhi.
// EPI 0: fp32 out.  EPI 1: exact GELU, split bf16 out (Chi/Clo).
// =============================================================================
#define NSTAGE 3
#define STAGE_BYTES 65536    // Ahi 16K | Alo 16K | Bhi 16K | Blo 16K
#define GT_SMEM (NSTAGE * STAGE_BYTES)

template <int EPI>
__global__ void __launch_bounds__(512, 1)
gemm_mma(const __nv_bfloat16* __restrict__ Ahi, const __nv_bfloat16* __restrict__ Alo,
         const __nv_bfloat16* __restrict__ Bhi, const __nv_bfloat16* __restrict__ Blo,
         const float* __restrict__ bias,
         float* __restrict__ C, __nv_bfloat16* __restrict__ Chi,
         __nv_bfloat16* __restrict__ Clo, int N, int K) {
    extern __shared__ __align__(1024) char sm[];
    const uint32_t smb = smem_u32(sm);
    const int tid = threadIdx.x;
    const int wid = tid >> 5, lane = tid & 31;
    const int bn = blockIdx.x * 128;
    const int bm = blockIdx.y * 128;
    const int nc = K >> 6;

    // ---- cp.async loader mapping: 1024 16B-chunks per 16KB matrix ----
    // chunk q: row = q>>3 (0..127), col16 = q&7; 2 chunks/thread/matrix
    auto ISSUE = [&](int c) {
        const uint32_t base = smb + (c % NSTAGE) * STAGE_BYTES;
        const int koff = c * 64;
#pragma unroll
        for (int i = 0; i < 2; ++i) {
            const int q = tid + 512 * i;
            const int r = q >> 3;
            const int c8 = q & 7;
            const uint32_t soff =
                (uint32_t)r * 128 + (((uint32_t)c8 * 16) ^ (((uint32_t)r & 7) << 4));
            const size_t ga = (size_t)(bm + r) * K + koff + c8 * 8;
            const size_t gb = (size_t)(bn + r) * K + koff + c8 * 8;
            cp16(base + soff,         Ahi + ga);
            cp16(base + 16384 + soff, Alo + ga);
            cp16(base + 32768 + soff, Bhi + gb);
            cp16(base + 49152 + soff, Blo + gb);
        }
        asm volatile("cp.async.commit_group;" ::: "memory");
    };

    // ---- mma-side addressing: 16 warps, 4x4 ----
    const int wm = wid & 3, wn = wid >> 2;
    const uint32_t xorm = (uint32_t)(lane & 7) << 4;
    const uint32_t rowA = (uint32_t)(wm * 32 + ((lane >> 3) & 1) * 8 + (lane & 7));
    const uint32_t kaddA = (uint32_t)(((lane >> 4) & 1) * 16);
    const uint32_t rowB = (uint32_t)(wn * 32 + ((lane >> 4) & 1) * 8 + (lane & 7));
    const uint32_t kaddB = (uint32_t)(((lane >> 3) & 1) * 16);

    float acc[2][4][4];
#pragma unroll
    for (int i = 0; i < 2; ++i)
#pragma unroll
        for (int j = 0; j < 4; ++j)
#pragma unroll
            for (int e = 0; e < 4; ++e) acc[i][j][e] = 0.f;

    auto MMA_CHUNK = [&](int s) {
        const uint32_t aHi = smb + s * STAGE_BYTES;
        const uint32_t aLo = aHi + 16384;
        const uint32_t bHi = aHi + 32768;
        const uint32_t bLo = aHi + 49152;
#pragma unroll
        for (int ks = 0; ks < 4; ++ks) {
            const uint32_t kb = ks * 32;
            uint32_t ah[2][4], al[2][4], bh[4][2], bl[4][2];
#pragma unroll
            for (int i = 0; i < 2; ++i) {
                uint32_t off = (rowA + i * 16) * 128 + ((kb + kaddA) ^ xorm);
                ldsm4(ah[i][0], ah[i][1], ah[i][2], ah[i][3], aHi + off);
                ldsm4(al[i][0], al[i][1], al[i][2], al[i][3], aLo + off);
            }
#pragma unroll
            for (int j2 = 0; j2 < 2; ++j2) {
                uint32_t off = (rowB + j2 * 16) * 128 + ((kb + kaddB) ^ xorm);
                ldsm4(bh[2 * j2][0], bh[2 * j2][1], bh[2 * j2 + 1][0],
                      bh[2 * j2 + 1][1], bHi + off);
                ldsm4(bl[2 * j2][0], bl[2 * j2][1], bl[2 * j2 + 1][0],
                      bl[2 * j2 + 1][1], bLo + off);
            }
#pragma unroll
            for (int i = 0; i < 2; ++i)
#pragma unroll
                for (int j = 0; j < 4; ++j) {
                    mma16816(acc[i][j], ah[i], bh[j]);
                    mma16816(acc[i][j], ah[i], bl[j]);
                    mma16816(acc[i][j], al[i], bh[j]);
                }
        }
    };

    // ---- 3-stage pipelined main loop ----
    ISSUE(0);
    ISSUE(1);
    for (int c = 0; c < nc; ++c) {
        if (c + 1 < nc)
            asm volatile("cp.async.wait_group 1;" ::: "memory");
        else
            asm volatile("cp.async.wait_group 0;" ::: "memory");
        __syncthreads();
        if (c + 2 < nc) ISSUE(c + 2);
        MMA_CHUNK(c % NSTAGE);
    }

    // ---- epilogue ----
#pragma unroll
    for (int i = 0; i < 2; ++i) {
        const int r0 = bm + wm * 32 + i * 16 + (lane >> 2);
#pragma unroll
        for (int j = 0; j < 4; ++j) {
            const int cc = bn + wn * 32 + j * 8 + (lane & 3) * 2;
            float2 bi = *reinterpret_cast<const float2*>(bias + cc);
            float o0 = acc[i][j][0] + bi.x, o1 = acc[i][j][1] + bi.y;
            float o2 = acc[i][j][2] + bi.x, o3 = acc[i][j][3] + bi.y;
            if (EPI == 1) {
                o0 = 0.5f * o0 * (1.0f + erff(o0 * 0.7071067811865475f));
                o1 = 0.5f * o1 * (1.0f + erff(o1 * 0.7071067811865475f));
                o2 = 0.5f * o2 * (1.0f + erff(o2 * 0.7071067811865475f));
                o3 = 0.5f * o3 * (1.0f + erff(o3 * 0.7071067811865475f));
                uint32_t h0, l0, h1, l1;
                split2(o0, o1, h0, l0);
                split2(o2, o3, h1, l1);
                *reinterpret_cast<uint32_t*>(Chi + (size_t)r0 * N + cc) = h0;
                *reinterpret_cast<uint32_t*>(Clo + (size_t)r0 * N + cc) = l0;
                *reinterpret_cast<uint32_t*>(Chi + (size_t)(r0 + 8) * N + cc) = h1;
                *reinterpret_cast<uint32_t*>(Clo + (size_t)(r0 + 8) * N + cc) = l1;
            } else {
                *reinterpret_cast<float2*>(C + (size_t)r0 * N + cc) =
                    make_float2(o0, o1);
                *reinterpret_cast<float2*>(C + (size_t)(r0 + 8) * N + cc) =
                    make_float2(o2, o3);
            }
        }
    }
}

// ---------------- fp32 -> bf16 hi/lo split (stream) ---------------------------
__global__ void split_kernel(const float4* __restrict__ src, uint2* __restrict__ hi,
                             uint2* __restrict__ lo, int n4) {
    int i = blockIdx.x * 256 + threadIdx.x;
    if (i < n4) {
        float4 v = src[i];
        uint2 h, l;
        split2(v.x, v.y, h.x, l.x);
        split2(v.z, v.w, h.y, l.y);
        hi[i] = h;
        lo[i] = l;
    }
}

// ---------------- prep: u_k, u_v, wsum_k, wsum_v ------------------------------
__global__ void prep_kernel(const float* __restrict__ cond_emb,
                            const float* __restrict__ Wk,
                            const float* __restrict__ Wv) {
    __shared__ __align__(16) float s_pad[256];
    int b = blockIdx.x;
    int t = threadIdx.x;
    if (t < 256) {
        int src = (t + 250) % 252;              // (t - 2) mod 252
        s_pad[t] = cond_emb[b * LRAW + src];
    }
    __syncthreads();
    int n = t;
    const float4* wk4 = reinterpret_cast<const float4*>(Wk + (size_t)n * 256);
    const float4* wv4 = reinterpret_cast<const float4*>(Wv + (size_t)n * 256);
    const float4* p4  = reinterpret_cast<const float4*>(s_pad);
    float uk = 0.f, uv = 0.f, sk = 0.f, sv = 0.f;
#pragma unroll 8
    for (int c = 0; c < 64; c++) {
        float4 p = p4[c];
        float4 k = wk4[c];
        float4 v = wv4[c];
        uk += p.x * k.x + p.y * k.y + p.z * k.z + p.w * k.w;
        uv += p.x * v.x + p.y * v.y + p.z * v.z + p.w * v.w;
        sk += k.x + k.y + k.z + k.w;
        sv += v.x + v.y + v.z + v.w;
    }
    g_uk[b * CDIM + n] = uk;
    g_uv[b * CDIM + n] = uv;
    if (b == 0) { g_wsk[n] = sk; g_wsv[n] = sv; }
}

// ---------------- attention (collapsed) + LN1: one warp per token -------------
// Writes query fp32 (residual for LN2) AND bf16 hi/lo split (FFN1 A operand).
__global__ __launch_bounds__(256)
void attn_ln1_kernel(const float* __restrict__ bv,
                     const float* __restrict__ conv_w,
                     const float* __restrict__ conv_b,
                     const float* __restrict__ ln1_w,
                     const float* __restrict__ ln1_b) {
    __shared__ __align__(16) float s_uk[CDIM], s_uv[CDIM], s_wsk[CDIM],
                                   s_wsv[CDIM], s_bv[CDIM], s_lw[CDIM],
                                   s_lb[CDIM], s_cw[SLEN], s_cb[SLEN];
    const int t = threadIdx.x;
    const int token0 = blockIdx.x * 8;
    const int b = token0 >> 10;
    for (int i = t; i < CDIM; i += 256) {
        s_uk[i] = g_uk[b * CDIM + i];
        s_uv[i] = g_uv[b * CDIM + i];
        s_wsk[i] = g_wsk[i];
        s_wsv[i] = g_wsv[i];
        s_bv[i] = bv[i];
        s_lw[i] = ln1_w[i];
        s_lb[i] = ln1_b[i];
    }
    if (t < SLEN) { s_cw[t] = conv_w[t]; s_cb[t] = conv_b[t]; }
    __syncthreads();

    const int warp = t >> 5, lane = t & 31;
    const int token = token0 + warp;
    const float4* qrow = reinterpret_cast<const float4*>(g_q + (size_t)token * CDIM);

    float4 qv[4];
    float A = 0.f, Bk = 0.f;
#pragma unroll
    for (int j = 0; j < 4; j++) {
        int i4 = j * 32 + lane;
        qv[j] = qrow[i4];
        float4 uk = reinterpret_cast<const float4*>(s_uk)[i4];
        float4 wk = reinterpret_cast<const float4*>(s_wsk)[i4];
        A  += qv[j].x * uk.x + qv[j].y * uk.y + qv[j].z * uk.z + qv[j].w * uk.w;
        Bk += qv[j].x * wk.x + qv[j].y * wk.y + qv[j].z * wk.z + qv[j].w * wk.w;
    }
#pragma unroll
    for (int o = 16; o > 0; o >>= 1) {
        A  += __shfl_xor_sync(0xffffffffu, A, o);
        Bk += __shfl_xor_sync(0xffffffffu, Bk, o);
    }

    const float scale = 0.04419417382415922f;   // 1/sqrt(512)
    float l[4], m = -1e30f;
#pragma unroll
    for (int j = 0; j < 4; j++) {
        int s = j * 32 + lane;
        l[j] = scale * (s_cw[s] * A + s_cb[s] * Bk);
        m = fmaxf(m, l[j]);
    }
#pragma unroll
    for (int o = 16; o > 0; o >>= 1)
        m = fmaxf(m, __shfl_xor_sync(0xffffffffu, m, o));

    float Z = 0.f, an = 0.f, bn = 0.f;
#pragma unroll
    for (int j = 0; j < 4; j++) {
        int s = j * 32 + lane;
        float e = expf(l[j] - m);
        Z += e;
        an += e * s_cw[s];
        bn += e * s_cb[s];
    }
#pragma unroll
    for (int o = 16; o > 0; o >>= 1) {
        Z  += __shfl_xor_sync(0xffffffffu, Z, o);
        an += __shfl_xor_sync(0xffffffffu, an, o);
        bn += __shfl_xor_sync(0xffffffffu, bn, o);
    }
    const float alpha = an / Z;
    const float beta  = bn / Z;

    float y[16];
    float sum = 0.f, sq = 0.f;
#pragma unroll
    for (int j = 0; j < 4; j++) {
        int i4 = j * 32 + lane;
        float4 uv = reinterpret_cast<const float4*>(s_uv)[i4];
        float4 wv = reinterpret_cast<const float4*>(s_wsv)[i4];
        float4 bb = reinterpret_cast<const float4*>(s_bv)[i4];
        float y0 = qv[j].x + alpha * uv.x + beta * wv.x + bb.x;
        float y1 = qv[j].y + alpha * uv.y + beta * wv.y + bb.y;
        float y2 = qv[j].z + alpha * uv.z + beta * wv.z + bb.z;
        float y3 = qv[j].w + alpha * uv.w + beta * wv.w + bb.w;
        y[j * 4 + 0] = y0; y[j * 4 + 1] = y1; y[j * 4 + 2] = y2; y[j * 4 + 3] = y3;
        sum += y0 + y1 + y2 + y3;
        sq  += y0 * y0 + y1 * y1 + y2 * y2 + y3 * y3;
    }
#pragma unroll
    for (int o = 16; o > 0; o >>= 1) {
        sum += __shfl_xor_sync(0xffffffffu, sum, o);
        sq  += __shfl_xor_sync(0xffffffffu, sq, o);
    }
    const float mean = sum * (1.f / 512.f);
    const float var  = sq * (1.f / 512.f) - mean * mean;
    const float rstd = rsqrtf(var + LN_EPS);

    float4* orow = reinterpret_cast<float4*>(g_query + (size_t)token * CDIM);
    uint2* hrow = reinterpret_cast<uint2*>(g_qyhi + (size_t)token * CDIM);
    uint2* lrow = reinterpret_cast<uint2*>(g_qylo + (size_t)token * CDIM);
#pragma unroll
    for (int j = 0; j < 4; j++) {
        int i4 = j * 32 + lane;
        float4 lw = reinterpret_cast<const float4*>(s_lw)[i4];
        float4 lb = reinterpret_cast<const float4*>(s_lb)[i4];
        float4 o;
        o.x = (y[j * 4 + 0] - mean) * rstd * lw.x + lb.x;
        o.y = (y[j * 4 + 1] - mean) * rstd * lw.y + lb.y;
        o.z = (y[j * 4 + 2] - mean) * rstd * lw.z + lb.z;
        o.w = (y[j * 4 + 3] - mean) * rstd * lw.w + lb.w;
        orow[i4] = o;
        uint2 h, l;
        split2(o.x, o.y, h.x, l.x);
        split2(o.z, o.w, h.y, l.y);
        hrow[i4] = h;
        lrow[i4] = l;
    }
}

// ---------------- LN2(query + ff) + x: one warp per token ---------------------
__global__ __launch_bounds__(256)
void ln2_add_kernel(const float* __restrict__ x,
                    const float* __restrict__ ln2_w,
                    const float* __restrict__ ln2_b,
                    float* __restrict__ out) {
    const int t = threadIdx.x;
    const int warp = t >> 5, lane = t & 31;
    const int token = blockIdx.x * 8 + warp;
    const float4* qr = reinterpret_cast<const float4*>(g_query + (size_t)token * CDIM);
    const float4* fr = reinterpret_cast<const float4*>(g_ff + (size_t)token * CDIM);
    const float4* xr = reinterpret_cast<const float4*>(x + (size_t)token * CDIM);
    float4* orow = reinterpret_cast<float4*>(out + (size_t)token * CDIM);

    float y[16];
    float4 xs[4];
    float sum = 0.f, sq = 0.f;
#pragma unroll
    for (int j = 0; j < 4; j++) {
        int i4 = j * 32 + lane;
        float4 a = qr[i4];
        float4 f = fr[i4];
        xs[j] = xr[i4];
        float y0 = a.x + f.x, y1 = a.y + f.y, y2 = a.z + f.z, y3 = a.w + f.w;
        y[j * 4 + 0] = y0; y[j * 4 + 1] = y1; y[j * 4 + 2] = y2; y[j * 4 + 3] = y3;
        sum += y0 + y1 + y2 + y3;
        sq  += y0 * y0 + y1 * y1 + y2 * y2 + y3 * y3;
    }
#pragma unroll
    for (int o = 16; o > 0; o >>= 1) {
        sum += __shfl_xor_sync(0xffffffffu, sum, o);
        sq  += __shfl_xor_sync(0xffffffffu, sq, o);
    }
    const float mean = sum * (1.f / 512.f);
    const float var  = sq * (1.f / 512.f) - mean * mean;
    const float rstd = rsqrtf(var + LN_EPS);

#pragma unroll
    for (int j = 0; j < 4; j++) {
        int i4 = j * 32 + lane;
        float4 lw = reinterpret_cast<const float4*>(ln2_w)[i4];
        float4 lb = reinterpret_cast<const float4*>(ln2_b)[i4];
        float4 o;
        o.x = (y[j * 4 + 0] - mean) * rstd * lw.x + lb.x + xs[j].x;
        o.y = (y[j * 4 + 1] - mean) * rstd * lw.y + lb.y + xs[j].y;
        o.z = (y[j * 4 + 2] - mean) * rstd * lw.z + lb.z + xs[j].z;
        o.w = (y[j * 4 + 3] - mean) * rstd * lw.w + lb.w + xs[j].w;
        orow[i4] = o;
    }
}

// ---------------- launch ------------------------------------------------------
extern "C" void kernel_launch(void* const* d_in, const int* in_sizes, int n_in,
                              void* d_out, int out_size) {
    const float* x        = (const float*)d_in[0];
    const float* cond_emb = (const float*)d_in[1];
    const float* Wq       = (const float*)d_in[2];
    const float* bq       = (const float*)d_in[3];
    const float* Wk       = (const float*)d_in[4];
    // d_in[5] = bk: constant shift along s, cancels in softmax
    const float* Wv       = (const float*)d_in[6];
    const float* bv       = (const float*)d_in[7];
    const float* conv_w   = (const float*)d_in[8];
    const float* conv_b   = (const float*)d_in[9];
    const float* ln1_w    = (const float*)d_in[10];
    const float* ln1_b    = (const float*)d_in[11];
    const float* W1       = (const float*)d_in[12];
    const float* b1       = (const float*)d_in[13];
    const float* W2       = (const float*)d_in[14];
    const float* b2       = (const float*)d_in[15];
    const float* ln2_w    = (const float*)d_in[16];
    const float* ln2_b    = (const float*)d_in[17];
    float* out            = (float*)d_out;

    float *pq, *pff;
    cudaGetSymbolAddress((void**)&pq, g_q);
    cudaGetSymbolAddress((void**)&pff, g_ff);
    __nv_bfloat16 *pxhi, *pxlo, *pqyhi, *pqylo, *phhi, *phlo;
    __nv_bfloat16 *pwqhi, *pwqlo, *pw1hi, *pw1lo, *pw2hi, *pw2lo;
    cudaGetSymbolAddress((void**)&pxhi, g_xhi);
    cudaGetSymbolAddress((void**)&pxlo, g_xlo);
    cudaGetSymbolAddress((void**)&pqyhi, g_qyhi);
    cudaGetSymbolAddress((void**)&pqylo, g_qylo);
    cudaGetSymbolAddress((void**)&phhi, g_hhi);
    cudaGetSymbolAddress((void**)&phlo, g_hlo);
    cudaGetSymbolAddress((void**)&pwqhi, g_wqhi);
    cudaGetSymbolAddress((void**)&pwqlo, g_wqlo);
    cudaGetSymbolAddress((void**)&pw1hi, g_w1hi);
    cudaGetSymbolAddress((void**)&pw1lo, g_w1lo);
    cudaGetSymbolAddress((void**)&pw2hi, g_w2hi);
    cudaGetSymbolAddress((void**)&pw2lo, g_w2lo);

    cudaFuncSetAttribute(gemm_mma<0>, cudaFuncAttributeMaxDynamicSharedMemorySize,
                         GT_SMEM);
    cudaFuncSetAttribute(gemm_mma<1>, cudaFuncAttributeMaxDynamicSharedMemorySize,
                         GT_SMEM);

    // 0) split inputs to bf16 hi/lo
    split_kernel<<<(MTOK * CDIM / 4 + 255) / 256, 256>>>(
        (const float4*)x, (uint2*)pxhi, (uint2*)pxlo, MTOK * CDIM / 4);
    split_kernel<<<(CDIM * CDIM / 4 + 255) / 256, 256>>>(
        (const float4*)Wq, (uint2*)pwqhi, (uint2*)pwqlo, CDIM * CDIM / 4);
    split_kernel<<<(2 * CDIM * CDIM / 4 + 255) / 256, 256>>>(
        (const float4*)W1, (uint2*)pw1hi, (uint2*)pw1lo, 2 * CDIM * CDIM / 4);
    split_kernel<<<(2 * CDIM * CDIM / 4 + 255) / 256, 256>>>(
        (const float4*)W2, (uint2*)pw2hi, (uint2*)pw2lo, 2 * CDIM * CDIM / 4);

    // 1) conditioner factorization
    prep_kernel<<<BATCH, 512>>>(cond_emb, Wk, Wv);

    // 2) q = x @ Wq^T + bq           [32768,512] x [512,512]
    gemm_mma<0><<<dim3(CDIM / 128, MTOK / 128), 512, GT_SMEM>>>(
        pxhi, pxlo, pwqhi, pwqlo, bq, pq, nullptr, nullptr, CDIM, CDIM);

    // 3) collapsed attention + LN1 -> query (fp32 + bf16 split)
    attn_ln1_kernel<<<MTOK / 8, 256>>>(bv, conv_w, conv_b, ln1_w, ln1_b);

    // 4) h = gelu(query @ W1^T + b1) -> bf16 split   [32768,1024]
    gemm_mma<1><<<dim3((2 * CDIM) / 128, MTOK / 128), 512, GT_SMEM>>>(
        pqyhi, pqylo, pw1hi, pw1lo, b1, nullptr, phhi, phlo, 2 * CDIM, CDIM);

    // 5) ff = h @ W2^T + b2          [32768,512] x [512,1024]
    gemm_mma<0><<<dim3(CDIM / 128, MTOK / 128), 512, GT_SMEM>>>(
        phhi, phlo, pw2hi, pw2lo, b2, pff, nullptr, nullptr, CDIM, 2 * CDIM);

    // 6) out = LN2(query + ff) + x
    ln2_add_kernel<<<MTOK / 8, 256>>>(x, ln2_w, ln2_b, out);
}

// round 11
// speedup vs baseline: 3.2912x; 1.2136x over previous
#include <cuda_runtime.h>
#include <cuda_bf16.h>
#include <cuda_fp16.h>
#include <math.h>
#include <stdint.h>

// Problem constants
#define BATCH 32
#define SEQT  1024
#define CDIM  512
#define LRAW  252
#define SLEN  128
#define MTOK  (BATCH * SEQT)   // 32768
#define LN_EPS 1e-5f

// ---------------- scratch (device globals; no allocation allowed) -------------
__device__ float g_q[MTOK * CDIM];            // q = x@Wq^T + bq
__device__ float g_query[MTOK * CDIM];        // LN1(q + attn_out) fp32 (for residual)
__device__ float g_ff[MTOK * CDIM];           // h@W2^T + b2
__device__ float g_uk[BATCH * CDIM];
__device__ float g_uv[BATCH * CDIM];
__device__ float g_wsk[CDIM];
__device__ float g_wsv[CDIM];

// bf16 hi/lo split operands (Q GEMM, 3-product)
__device__ uint16_t g_xhi[MTOK * CDIM],  g_xlo[MTOK * CDIM];
__device__ uint16_t g_wqhi[CDIM * CDIM], g_wqlo[CDIM * CDIM];
// fp16 operands (FFN GEMMs, 2-product: activations split, weights single)
__device__ uint16_t g_qyhi[MTOK * CDIM],    g_qylo[MTOK * CDIM];     // query split
__device__ uint16_t g_hhi[MTOK * 2 * CDIM], g_hlo[MTOK * 2 * CDIM];  // gelu out split
__device__ uint16_t g_w1h[2 * CDIM * CDIM];                          // W1 fp16
__device__ uint16_t g_w2h[CDIM * 2 * CDIM];                          // W2 fp16

// =============================================================================
// helpers
// =============================================================================
__device__ __forceinline__ uint32_t smem_u32(const void* p) {
    uint32_t a;
    asm("{ .reg .u64 t; cvta.to.shared.u64 t, %1; cvt.u32.u64 %0, t; }"
        : "=r"(a) : "l"(p));
    return a;
}

// fp32 pair -> packed bf16 hi / lo
__device__ __forceinline__ void split2(float a, float b, uint32_t& hi, uint32_t& lo) {
    __nv_bfloat16 ha = __float2bfloat16(a), hb = __float2bfloat16(b);
    __nv_bfloat16 la = __float2bfloat16(a - __bfloat162float(ha));
    __nv_bfloat16 lb = __float2bfloat16(b - __bfloat162float(hb));
    hi = (uint32_t)__bfloat16_as_ushort(ha) | ((uint32_t)__bfloat16_as_ushort(hb) << 16);
    lo = (uint32_t)__bfloat16_as_ushort(la) | ((uint32_t)__bfloat16_as_ushort(lb) << 16);
}

// fp32 pair -> packed fp16 hi / lo
__device__ __forceinline__ void split2h(float a, float b, uint32_t& hi, uint32_t& lo) {
    __half ha = __float2half(a), hb = __float2half(b);
    __half la = __float2half(a - __half2float(ha));
    __half lb = __float2half(b - __half2float(hb));
    hi = (uint32_t)__half_as_ushort(ha) | ((uint32_t)__half_as_ushort(hb) << 16);
    lo = (uint32_t)__half_as_ushort(la) | ((uint32_t)__half_as_ushort(lb) << 16);
}

__device__ __forceinline__ void ldsm4(uint32_t& r0, uint32_t& r1, uint32_t& r2,
                                      uint32_t& r3, uint32_t addr) {
    asm volatile("ldmatrix.sync.aligned.m8n8.x4.shared.b16 {%0,%1,%2,%3}, [%4];"
                 : "=r"(r0), "=r"(r1), "=r"(r2), "=r"(r3) : "r"(addr));
}

template <int PREC>   // 0 = bf16, 1 = fp16
__device__ __forceinline__ void mma_any(float* d, const uint32_t* a,
                                        const uint32_t* b) {
    if (PREC == 0)
        asm volatile(
            "mma.sync.aligned.m16n8k16.row.col.f32.bf16.bf16.f32 "
            "{%0,%1,%2,%3}, {%4,%5,%6,%7}, {%8,%9}, {%0,%1,%2,%3};"
            : "+f"(d[0]), "+f"(d[1]), "+f"(d[2]), "+f"(d[3])
            : "r"(a[0]), "r"(a[1]), "r"(a[2]), "r"(a[3]), "r"(b[0]), "r"(b[1]));
    else
        asm volatile(
            "mma.sync.aligned.m16n8k16.row.col.f32.f16.f16.f32 "
            "{%0,%1,%2,%3}, {%4,%5,%6,%7}, {%8,%9}, {%0,%1,%2,%3};"
            : "+f"(d[0]), "+f"(d[1]), "+f"(d[2]), "+f"(d[3])
            : "r"(a[0]), "r"(a[1]), "r"(a[2]), "r"(a[3]), "r"(b[0]), "r"(b[1]));
}

__device__ __forceinline__ void cp16(uint32_t dst, const void* src) {
    asm volatile("cp.async.cg.shared.global [%0], [%1], 16;"
                 :: "r"(dst), "l"(src));
}

// =============================================================================
// Pipelined split GEMM (mma.sync): C[M,N] = A[M,K] * B[N,K]^T + bias
// CTA 128x128, K-chunk 64, XOR swizzle, cp.async 3-stage, 512 thr = 16 warps.
// PREC 0 (bf16, 3-product): D += Ahi*Bhi + Ahi*Blo + Alo*Bhi   (stage 64KB)
// PREC 1 (fp16, 2-product): D += Ahi*Bhi + Alo*Bhi             (stage 48KB)
// EPI 0: fp32 out.  EPI 1: exact GELU, split fp16 out (Chi/Clo).
// =============================================================================
#define NSTAGE 3

template <int EPI, int PREC>
__global__ void __launch_bounds__(512, 1)
gemm_mma(const uint16_t* __restrict__ Ahi, const uint16_t* __restrict__ Alo,
         const uint16_t* __restrict__ Bhi, const uint16_t* __restrict__ Blo,
         const float* __restrict__ bias,
         float* __restrict__ C, uint16_t* __restrict__ Chi,
         uint16_t* __restrict__ Clo, int N, int K) {
    constexpr uint32_t STAGE = PREC ? 49152u : 65536u;   // matrices of 16KB
    extern __shared__ __align__(1024) char sm[];
    const uint32_t smb = smem_u32(sm);
    const int tid = threadIdx.x;
    const int wid = tid >> 5, lane = tid & 31;
    const int bn = blockIdx.x * 128;
    const int bm = blockIdx.y * 128;
    const int nc = K >> 6;

    // ---- cp.async loader: matrices [Ahi|Alo|Bhi(|Blo)], 1024 16B-chunks each ----
    auto ISSUE = [&](int c) {
        const uint32_t base = smb + (c % NSTAGE) * STAGE;
        const int koff = c * 64;
        constexpr int NCH = PREC ? 6 : 8;
#pragma unroll
        for (int i = 0; i < NCH; ++i) {
            const int q = tid + 512 * i;
            const int mat = q >> 10;            // = i>>1
            const int w = q & 1023;
            const int r = w >> 3;
            const int c8 = w & 7;
            const uint32_t soff = (uint32_t)mat * 16384u + (uint32_t)r * 128u +
                (((uint32_t)c8 * 16u) ^ (((uint32_t)r & 7u) << 4));
            const uint16_t* src;
            size_t ga = (size_t)(bm + r) * K + koff + c8 * 8;
            size_t gb = (size_t)(bn + r) * K + koff + c8 * 8;
            if (mat == 0)      src = Ahi + ga;
            else if (mat == 1) src = Alo + ga;
            else if (mat == 2) src = Bhi + gb;
            else               src = Blo + gb;
            cp16(base + soff, src);
        }
        asm volatile("cp.async.commit_group;" ::: "memory");
    };

    // ---- mma-side addressing: 16 warps, 4x4, warp tile 32x32 ----
    const int wm = wid & 3, wn = wid >> 2;
    const uint32_t xorm = (uint32_t)(lane & 7) << 4;
    const uint32_t rowA = (uint32_t)(wm * 32 + ((lane >> 3) & 1) * 8 + (lane & 7));
    const uint32_t kaddA = (uint32_t)(((lane >> 4) & 1) * 16);
    const uint32_t rowB = (uint32_t)(wn * 32 + ((lane >> 4) & 1) * 8 + (lane & 7));
    const uint32_t kaddB = (uint32_t)(((lane >> 3) & 1) * 16);

    float acc[2][4][4];
#pragma unroll
    for (int i = 0; i < 2; ++i)
#pragma unroll
        for (int j = 0; j < 4; ++j)
#pragma unroll
            for (int e = 0; e < 4; ++e) acc[i][j][e] = 0.f;

    auto MMA_CHUNK = [&](int s) {
        const uint32_t aHi = smb + s * STAGE;
        const uint32_t aLo = aHi + 16384;
        const uint32_t bHi = aHi + 32768;
        const uint32_t bLo = aHi + 49152;   // only valid when PREC==0
#pragma unroll
        for (int ks = 0; ks < 4; ++ks) {
            const uint32_t kb = ks * 32;
            uint32_t ah[2][4], al[2][4], bh[4][2], bl[4][2];
#pragma unroll
            for (int i = 0; i < 2; ++i) {
                uint32_t off = (rowA + i * 16) * 128 + ((kb + kaddA) ^ xorm);
                ldsm4(ah[i][0], ah[i][1], ah[i][2], ah[i][3], aHi + off);
                ldsm4(al[i][0], al[i][1], al[i][2], al[i][3], aLo + off);
            }
#pragma unroll
            for (int j2 = 0; j2 < 2; ++j2) {
                uint32_t off = (rowB + j2 * 16) * 128 + ((kb + kaddB) ^ xorm);
                ldsm4(bh[2 * j2][0], bh[2 * j2][1], bh[2 * j2 + 1][0],
                      bh[2 * j2 + 1][1], bHi + off);
                if (PREC == 0)
                    ldsm4(bl[2 * j2][0], bl[2 * j2][1], bl[2 * j2 + 1][0],
                          bl[2 * j2 + 1][1], bLo + off);
            }
#pragma unroll
            for (int i = 0; i < 2; ++i)
#pragma unroll
                for (int j = 0; j < 4; ++j) {
                    mma_any<PREC>(acc[i][j], ah[i], bh[j]);
                    if (PREC == 0) mma_any<PREC>(acc[i][j], ah[i], bl[j]);
                    mma_any<PREC>(acc[i][j], al[i], bh[j]);
                }
        }
    };

    // ---- 3-stage pipelined main loop ----
    ISSUE(0);
    ISSUE(1);
    for (int c = 0; c < nc; ++c) {
        if (c + 1 < nc)
            asm volatile("cp.async.wait_group 1;" ::: "memory");
        else
            asm volatile("cp.async.wait_group 0;" ::: "memory");
        __syncthreads();
        if (c + 2 < nc) ISSUE(c + 2);
        MMA_CHUNK(c % NSTAGE);
    }

    // ---- epilogue ----
#pragma unroll
    for (int i = 0; i < 2; ++i) {
        const int r0 = bm + wm * 32 + i * 16 + (lane >> 2);
#pragma unroll
        for (int j = 0; j < 4; ++j) {
            const int cc = bn + wn * 32 + j * 8 + (lane & 3) * 2;
            float2 bi = *reinterpret_cast<const float2*>(bias + cc);
            float o0 = acc[i][j][0] + bi.x, o1 = acc[i][j][1] + bi.y;
            float o2 = acc[i][j][2] + bi.x, o3 = acc[i][j][3] + bi.y;
            if (EPI == 1) {
                o0 = 0.5f * o0 * (1.0f + erff(o0 * 0.7071067811865475f));
                o1 = 0.5f * o1 * (1.0f + erff(o1 * 0.7071067811865475f));
                o2 = 0.5f * o2 * (1.0f + erff(o2 * 0.7071067811865475f));
                o3 = 0.5f * o3 * (1.0f + erff(o3 * 0.7071067811865475f));
                uint32_t h0, l0, h1, l1;
                split2h(o0, o1, h0, l0);
                split2h(o2, o3, h1, l1);
                *reinterpret_cast<uint32_t*>(Chi + (size_t)r0 * N + cc) = h0;
                *reinterpret_cast<uint32_t*>(Clo + (size_t)r0 * N + cc) = l0;
                *reinterpret_cast<uint32_t*>(Chi + (size_t)(r0 + 8) * N + cc) = h1;
                *reinterpret_cast<uint32_t*>(Clo + (size_t)(r0 + 8) * N + cc) = l1;
            } else {
                *reinterpret_cast<float2*>(C + (size_t)r0 * N + cc) =
                    make_float2(o0, o1);
                *reinterpret_cast<float2*>(C + (size_t)(r0 + 8) * N + cc) =
                    make_float2(o2, o3);
            }
        }
    }
}

// ---------------- fp32 -> bf16 hi/lo split (stream) ---------------------------
__global__ void split_kernel(const float4* __restrict__ src, uint2* __restrict__ hi,
                             uint2* __restrict__ lo, int n4) {
    int i = blockIdx.x * 256 + threadIdx.x;
    if (i < n4) {
        float4 v = src[i];
        uint2 h, l;
        split2(v.x, v.y, h.x, l.x);
        split2(v.z, v.w, h.y, l.y);
        hi[i] = h;
        lo[i] = l;
    }
}

// ---------------- fp32 -> fp16 convert (stream) -------------------------------
__global__ void cvt_h_kernel(const float4* __restrict__ src, uint2* __restrict__ dst,
                             int n4) {
    int i = blockIdx.x * 256 + threadIdx.x;
    if (i < n4) {
        float4 v = src[i];
        uint2 o;
        o.x = (uint32_t)__half_as_ushort(__float2half(v.x)) |
              ((uint32_t)__half_as_ushort(__float2half(v.y)) << 16);
        o.y = (uint32_t)__half_as_ushort(__float2half(v.z)) |
              ((uint32_t)__half_as_ushort(__float2half(v.w)) << 16);
        dst[i] = o;
    }
}

// ---------------- prep: u_k, u_v, wsum_k, wsum_v ------------------------------
__global__ void prep_kernel(const float* __restrict__ cond_emb,
                            const float* __restrict__ Wk,
                            const float* __restrict__ Wv) {
    __shared__ __align__(16) float s_pad[256];
    int b = blockIdx.x;
    int t = threadIdx.x;
    if (t < 256) {
        int src = (t + 250) % 252;              // (t - 2) mod 252
        s_pad[t] = cond_emb[b * LRAW + src];
    }
    __syncthreads();
    int n = t;
    const float4* wk4 = reinterpret_cast<const float4*>(Wk + (size_t)n * 256);
    const float4* wv4 = reinterpret_cast<const float4*>(Wv + (size_t)n * 256);
    const float4* p4  = reinterpret_cast<const float4*>(s_pad);
    float uk = 0.f, uv = 0.f, sk = 0.f, sv = 0.f;
#pragma unroll 8
    for (int c = 0; c < 64; c++) {
        float4 p = p4[c];
        float4 k = wk4[c];
        float4 v = wv4[c];
        uk += p.x * k.x + p.y * k.y + p.z * k.z + p.w * k.w;
        uv += p.x * v.x + p.y * v.y + p.z * v.z + p.w * v.w;
        sk += k.x + k.y + k.z + k.w;
        sv += v.x + v.y + v.z + v.w;
    }
    g_uk[b * CDIM + n] = uk;
    g_uv[b * CDIM + n] = uv;
    if (b == 0) { g_wsk[n] = sk; g_wsv[n] = sv; }
}

// ---------------- attention (collapsed) + LN1: one warp per token -------------
// Writes query fp32 (residual for LN2) AND fp16 hi/lo split (FFN1 A operand).
__global__ __launch_bounds__(256)
void attn_ln1_kernel(const float* __restrict__ bv,
                     const float* __restrict__ conv_w,
                     const float* __restrict__ conv_b,
                     const float* __restrict__ ln1_w,
                     const float* __restrict__ ln1_b) {
    __shared__ __align__(16) float s_uk[CDIM], s_uv[CDIM], s_wsk[CDIM],
                                   s_wsv[CDIM], s_bv[CDIM], s_lw[CDIM],
                                   s_lb[CDIM], s_cw[SLEN], s_cb[SLEN];
    const int t = threadIdx.x;
    const int token0 = blockIdx.x * 8;
    const int b = token0 >> 10;
    for (int i = t; i < CDIM; i += 256) {
        s_uk[i] = g_uk[b * CDIM + i];
        s_uv[i] = g_uv[b * CDIM + i];
        s_wsk[i] = g_wsk[i];
        s_wsv[i] = g_wsv[i];
        s_bv[i] = bv[i];
        s_lw[i] = ln1_w[i];
        s_lb[i] = ln1_b[i];
    }
    if (t < SLEN) { s_cw[t] = conv_w[t]; s_cb[t] = conv_b[t]; }
    __syncthreads();

    const int warp = t >> 5, lane = t & 31;
    const int token = token0 + warp;
    const float4* qrow = reinterpret_cast<const float4*>(g_q + (size_t)token * CDIM);

    float4 qv[4];
    float A = 0.f, Bk = 0.f;
#pragma unroll
    for (int j = 0; j < 4; j++) {
        int i4 = j * 32 + lane;
        qv[j] = qrow[i4];
        float4 uk = reinterpret_cast<const float4*>(s_uk)[i4];
        float4 wk = reinterpret_cast<const float4*>(s_wsk)[i4];
        A  += qv[j].x * uk.x + qv[j].y * uk.y + qv[j].z * uk.z + qv[j].w * uk.w;
        Bk += qv[j].x * wk.x + qv[j].y * wk.y + qv[j].z * wk.z + qv[j].w * wk.w;
    }
#pragma unroll
    for (int o = 16; o > 0; o >>= 1) {
        A  += __shfl_xor_sync(0xffffffffu, A, o);
        Bk += __shfl_xor_sync(0xffffffffu, Bk, o);
    }

    const float scale = 0.04419417382415922f;   // 1/sqrt(512)
    float l[4], m = -1e30f;
#pragma unroll
    for (int j = 0; j < 4; j++) {
        int s = j * 32 + lane;
        l[j] = scale * (s_cw[s] * A + s_cb[s] * Bk);
        m = fmaxf(m, l[j]);
    }
#pragma unroll
    for (int o = 16; o > 0; o >>= 1)
        m = fmaxf(m, __shfl_xor_sync(0xffffffffu, m, o));

    float Z = 0.f, an = 0.f, bn = 0.f;
#pragma unroll
    for (int j = 0; j < 4; j++) {
        int s = j * 32 + lane;
        float e = expf(l[j] - m);
        Z += e;
        an += e * s_cw[s];
        bn += e * s_cb[s];
    }
#pragma unroll
    for (int o = 16; o > 0; o >>= 1) {
        Z  += __shfl_xor_sync(0xffffffffu, Z, o);
        an += __shfl_xor_sync(0xffffffffu, an, o);
        bn += __shfl_xor_sync(0xffffffffu, bn, o);
    }
    const float alpha = an / Z;
    const float beta  = bn / Z;

    float y[16];
    float sum = 0.f, sq = 0.f;
#pragma unroll
    for (int j = 0; j < 4; j++) {
        int i4 = j * 32 + lane;
        float4 uv = reinterpret_cast<const float4*>(s_uv)[i4];
        float4 wv = reinterpret_cast<const float4*>(s_wsv)[i4];
        float4 bb = reinterpret_cast<const float4*>(s_bv)[i4];
        float y0 = qv[j].x + alpha * uv.x + beta * wv.x + bb.x;
        float y1 = qv[j].y + alpha * uv.y + beta * wv.y + bb.y;
        float y2 = qv[j].z + alpha * uv.z + beta * wv.z + bb.z;
        float y3 = qv[j].w + alpha * uv.w + beta * wv.w + bb.w;
        y[j * 4 + 0] = y0; y[j * 4 + 1] = y1; y[j * 4 + 2] = y2; y[j * 4 + 3] = y3;
        sum += y0 + y1 + y2 + y3;
        sq  += y0 * y0 + y1 * y1 + y2 * y2 + y3 * y3;
    }
#pragma unroll
    for (int o = 16; o > 0; o >>= 1) {
        sum += __shfl_xor_sync(0xffffffffu, sum, o);
        sq  += __shfl_xor_sync(0xffffffffu, sq, o);
    }
    const float mean = sum * (1.f / 512.f);
    const float var  = sq * (1.f / 512.f) - mean * mean;
    const float rstd = rsqrtf(var + LN_EPS);

    float4* orow = reinterpret_cast<float4*>(g_query + (size_t)token * CDIM);
    uint2* hrow = reinterpret_cast<uint2*>(g_qyhi + (size_t)token * CDIM);
    uint2* lrow = reinterpret_cast<uint2*>(g_qylo + (size_t)token * CDIM);
#pragma unroll
    for (int j = 0; j < 4; j++) {
        int i4 = j * 32 + lane;
        float4 lw = reinterpret_cast<const float4*>(s_lw)[i4];
        float4 lb = reinterpret_cast<const float4*>(s_lb)[i4];
        float4 o;
        o.x = (y[j * 4 + 0] - mean) * rstd * lw.x + lb.x;
        o.y = (y[j * 4 + 1] - mean) * rstd * lw.y + lb.y;
        o.z = (y[j * 4 + 2] - mean) * rstd * lw.z + lb.z;
        o.w = (y[j * 4 + 3] - mean) * rstd * lw.w + lb.w;
        orow[i4] = o;
        uint2 h, l;
        split2h(o.x, o.y, h.x, l.x);
        split2h(o.z, o.w, h.y, l.y);
        hrow[i4] = h;
        lrow[i4] = l;
    }
}

// ---------------- LN2(query + ff) + x: one warp per token ---------------------
__global__ __launch_bounds__(256)
void ln2_add_kernel(const float* __restrict__ x,
                    const float* __restrict__ ln2_w,
                    const float* __restrict__ ln2_b,
                    float* __restrict__ out) {
    const int t = threadIdx.x;
    const int warp = t >> 5, lane = t & 31;
    const int token = blockIdx.x * 8 + warp;
    const float4* qr = reinterpret_cast<const float4*>(g_query + (size_t)token * CDIM);
    const float4* fr = reinterpret_cast<const float4*>(g_ff + (size_t)token * CDIM);
    const float4* xr = reinterpret_cast<const float4*>(x + (size_t)token * CDIM);
    float4* orow = reinterpret_cast<float4*>(out + (size_t)token * CDIM);

    float y[16];
    float4 xs[4];
    float sum = 0.f, sq = 0.f;
#pragma unroll
    for (int j = 0; j < 4; j++) {
        int i4 = j * 32 + lane;
        float4 a = qr[i4];
        float4 f = fr[i4];
        xs[j] = xr[i4];
        float y0 = a.x + f.x, y1 = a.y + f.y, y2 = a.z + f.z, y3 = a.w + f.w;
        y[j * 4 + 0] = y0; y[j * 4 + 1] = y1; y[j * 4 + 2] = y2; y[j * 4 + 3] = y3;
        sum += y0 + y1 + y2 + y3;
        sq  += y0 * y0 + y1 * y1 + y2 * y2 + y3 * y3;
    }
#pragma unroll
    for (int o = 16; o > 0; o >>= 1) {
        sum += __shfl_xor_sync(0xffffffffu, sum, o);
        sq  += __shfl_xor_sync(0xffffffffu, sq, o);
    }
    const float mean = sum * (1.f / 512.f);
    const float var  = sq * (1.f / 512.f) - mean * mean;
    const float rstd = rsqrtf(var + LN_EPS);

#pragma unroll
    for (int j = 0; j < 4; j++) {
        int i4 = j * 32 + lane;
        float4 lw = reinterpret_cast<const float4*>(ln2_w)[i4];
        float4 lb = reinterpret_cast<const float4*>(ln2_b)[i4];
        float4 o;
        o.x = (y[j * 4 + 0] - mean) * rstd * lw.x + lb.x + xs[j].x;
        o.y = (y[j * 4 + 1] - mean) * rstd * lw.y + lb.y + xs[j].y;
        o.z = (y[j * 4 + 2] - mean) * rstd * lw.z + lb.z + xs[j].z;
        o.w = (y[j * 4 + 3] - mean) * rstd * lw.w + lb.w + xs[j].w;
        orow[i4] = o;
    }
}

// ---------------- launch ------------------------------------------------------
extern "C" void kernel_launch(void* const* d_in, const int* in_sizes, int n_in,
                              void* d_out, int out_size) {
    const float* x        = (const float*)d_in[0];
    const float* cond_emb = (const float*)d_in[1];
    const float* Wq       = (const float*)d_in[2];
    const float* bq       = (const float*)d_in[3];
    const float* Wk       = (const float*)d_in[4];
    // d_in[5] = bk: constant shift along s, cancels in softmax
    const float* Wv       = (const float*)d_in[6];
    const float* bv       = (const float*)d_in[7];
    const float* conv_w   = (const float*)d_in[8];
    const float* conv_b   = (const float*)d_in[9];
    const float* ln1_w    = (const float*)d_in[10];
    const float* ln1_b    = (const float*)d_in[11];
    const float* W1       = (const float*)d_in[12];
    const float* b1       = (const float*)d_in[13];
    const float* W2       = (const float*)d_in[14];
    const float* b2       = (const float*)d_in[15];
    const float* ln2_w    = (const float*)d_in[16];
    const float* ln2_b    = (const float*)d_in[17];
    float* out            = (float*)d_out;

    float *pq, *pff;
    cudaGetSymbolAddress((void**)&pq, g_q);
    cudaGetSymbolAddress((void**)&pff, g_ff);
    uint16_t *pxhi, *pxlo, *pwqhi, *pwqlo;
    uint16_t *pqyhi, *pqylo, *phhi, *phlo, *pw1h, *pw2h;
    cudaGetSymbolAddress((void**)&pxhi, g_xhi);
    cudaGetSymbolAddress((void**)&pxlo, g_xlo);
    cudaGetSymbolAddress((void**)&pwqhi, g_wqhi);
    cudaGetSymbolAddress((void**)&pwqlo, g_wqlo);
    cudaGetSymbolAddress((void**)&pqyhi, g_qyhi);
    cudaGetSymbolAddress((void**)&pqylo, g_qylo);
    cudaGetSymbolAddress((void**)&phhi, g_hhi);
    cudaGetSymbolAddress((void**)&phlo, g_hlo);
    cudaGetSymbolAddress((void**)&pw1h, g_w1h);
    cudaGetSymbolAddress((void**)&pw2h, g_w2h);

    const int SMEM_BF = NSTAGE * 65536;   // 192 KB
    const int SMEM_FP = NSTAGE * 49152;   // 144 KB
    cudaFuncSetAttribute(gemm_mma<0, 0>,
                         cudaFuncAttributeMaxDynamicSharedMemorySize, SMEM_BF);
    cudaFuncSetAttribute(gemm_mma<1, 1>,
                         cudaFuncAttributeMaxDynamicSharedMemorySize, SMEM_FP);
    cudaFuncSetAttribute(gemm_mma<0, 1>,
                         cudaFuncAttributeMaxDynamicSharedMemorySize, SMEM_FP);

    // 0) operand prep
    split_kernel<<<(MTOK * CDIM / 4 + 255) / 256, 256>>>(
        (const float4*)x, (uint2*)pxhi, (uint2*)pxlo, MTOK * CDIM / 4);
    split_kernel<<<(CDIM * CDIM / 4 + 255) / 256, 256>>>(
        (const float4*)Wq, (uint2*)pwqhi, (uint2*)pwqlo, CDIM * CDIM / 4);
    cvt_h_kernel<<<(2 * CDIM * CDIM / 4 + 255) / 256, 256>>>(
        (const float4*)W1, (uint2*)pw1h, 2 * CDIM * CDIM / 4);
    cvt_h_kernel<<<(2 * CDIM * CDIM / 4 + 255) / 256, 256>>>(
        (const float4*)W2, (uint2*)pw2h, 2 * CDIM * CDIM / 4);

    // 1) conditioner factorization
    prep_kernel<<<BATCH, 512>>>(cond_emb, Wk, Wv);

    // 2) q = x @ Wq^T + bq   (bf16 3-product, rel err ~2^-18)
    gemm_mma<0, 0><<<dim3(CDIM / 128, MTOK / 128), 512, SMEM_BF>>>(
        pxhi, pxlo, pwqhi, pwqlo, bq, pq, nullptr, nullptr, CDIM, CDIM);

    // 3) collapsed attention + LN1 -> query (fp32 + fp16 split)
    attn_ln1_kernel<<<MTOK / 8, 256>>>(bv, conv_w, conv_b, ln1_w, ln1_b);

    // 4) h = gelu(query @ W1^T + b1) -> fp16 split  (fp16 2-product)
    gemm_mma<1, 1><<<dim3((2 * CDIM) / 128, MTOK / 128), 512, SMEM_FP>>>(
        pqyhi, pqylo, pw1h, nullptr, b1, nullptr, phhi, phlo, 2 * CDIM, CDIM);

    // 5) ff = h @ W2^T + b2   (fp16 2-product)
    gemm_mma<0, 1><<<dim3(CDIM / 128, MTOK / 128), 512, SMEM_FP>>>(
        phhi, phlo, pw2h, nullptr, b2, pff, nullptr, nullptr, CDIM, 2 * CDIM);

    // 6) out = LN2(query + ff) + x
    ln2_add_kernel<<<MTOK / 8, 256>>>(x, ln2_w, ln2_b, out);
}

// round 13
// speedup vs baseline: 4.7886x; 1.4550x over previous
#include <cuda_runtime.h>
#include <cuda_bf16.h>
#include <cuda_fp16.h>
#include <math.h>
#include <stdint.h>

// Problem constants
#define BATCH 32
#define SEQT  1024
#define CDIM  512
#define LRAW  252
#define SLEN  128
#define MTOK  (BATCH * SEQT)   // 32768
#define LN_EPS 1e-5f

// ---------------- scratch (device globals; no allocation allowed) -------------
__device__ float g_q[MTOK * CDIM];            // q = x@Wq^T + bq (fp32)
__device__ float g_query[MTOK * CDIM];        // LN1(q + attn_out) fp32 (residual)
__device__ float g_ff[MTOK * CDIM];           // h@W2^T + b2
__device__ float g_uk[BATCH * CDIM];
__device__ float g_uv[BATCH * CDIM];
__device__ float g_wsk[CDIM];
__device__ float g_wsv[CDIM];

// fp16 single-precision operands
__device__ uint16_t g_xh[MTOK * CDIM];            // x fp16
__device__ uint16_t g_qyh[MTOK * CDIM];           // query fp16
__device__ uint16_t g_hh[MTOK * 2 * CDIM];        // gelu out fp16
__device__ uint16_t g_wqh[CDIM * CDIM];           // Wq fp16
__device__ uint16_t g_w1h[2 * CDIM * CDIM];       // W1 fp16
__device__ uint16_t g_w2h[CDIM * 2 * CDIM];       // W2 fp16

// =============================================================================
// helpers
// =============================================================================
__device__ __forceinline__ uint32_t smem_u32(const void* p) {
    uint32_t a;
    asm("{ .reg .u64 t; cvta.to.shared.u64 t, %1; cvt.u32.u64 %0, t; }"
        : "=r"(a) : "l"(p));
    return a;
}

__device__ __forceinline__ uint32_t packh(float a, float b) {
    return (uint32_t)__half_as_ushort(__float2half(a)) |
           ((uint32_t)__half_as_ushort(__float2half(b)) << 16);
}

__device__ __forceinline__ void ldsm4(uint32_t& r0, uint32_t& r1, uint32_t& r2,
                                      uint32_t& r3, uint32_t addr) {
    asm volatile("ldmatrix.sync.aligned.m8n8.x4.shared.b16 {%0,%1,%2,%3}, [%4];"
                 : "=r"(r0), "=r"(r1), "=r"(r2), "=r"(r3) : "r"(addr));
}

__device__ __forceinline__ void mma_h(float* d, const uint32_t* a,
                                      const uint32_t* b) {
    asm volatile(
        "mma.sync.aligned.m16n8k16.row.col.f32.f16.f16.f32 "
        "{%0,%1,%2,%3}, {%4,%5,%6,%7}, {%8,%9}, {%0,%1,%2,%3};"
        : "+f"(d[0]), "+f"(d[1]), "+f"(d[2]), "+f"(d[3])
        : "r"(a[0]), "r"(a[1]), "r"(a[2]), "r"(a[3]), "r"(b[0]), "r"(b[1]));
}

__device__ __forceinline__ void cp16(uint32_t dst, const void* src) {
    asm volatile("cp.async.cg.shared.global [%0], [%1], 16;"
                 :: "r"(dst), "l"(src));
}

// =============================================================================
// Pipelined fp16 GEMM (mma.sync): C[M,N] = A[M,K] * B[N,K]^T + bias
// CTA 128x128, K-chunk 64, XOR swizzle, cp.async 3-stage (32KB/stage),
// 512 threads = 16 warps (4x4), warp tile 32x32.
// EPI 0: fp32 out.  EPI 1: exact GELU, fp16 out (Ch).
// =============================================================================
#define NSTAGE 3
#define STAGE 32768u
#define GT_SMEM (NSTAGE * STAGE)

template <int EPI>
__global__ void __launch_bounds__(512, 1)
gemm_h(const uint16_t* __restrict__ Ah, const uint16_t* __restrict__ Bh,
       const float* __restrict__ bias,
       float* __restrict__ C, uint16_t* __restrict__ Ch, int N, int K) {
    extern __shared__ __align__(1024) char sm[];
    const uint32_t smb = smem_u32(sm);
    const int tid = threadIdx.x;
    const int wid = tid >> 5, lane = tid & 31;
    const int bn = blockIdx.x * 128;
    const int bm = blockIdx.y * 128;
    const int nc = K >> 6;

    // ---- cp.async loader: [Ah | Bh], 1024 16B-chunks each ----
    auto ISSUE = [&](int c) {
        const uint32_t base = smb + (c % NSTAGE) * STAGE;
        const int koff = c * 64;
#pragma unroll
        for (int i = 0; i < 4; ++i) {
            const int q = tid + 512 * i;
            const int mat = q >> 10;           // 0 = A, 1 = B
            const int w = q & 1023;
            const int r = w >> 3;
            const int c8 = w & 7;
            const uint32_t soff = (uint32_t)mat * 16384u + (uint32_t)r * 128u +
                (((uint32_t)c8 * 16u) ^ (((uint32_t)r & 7u) << 4));
            const uint16_t* src = mat == 0
                ? Ah + (size_t)(bm + r) * K + koff + c8 * 8
                : Bh + (size_t)(bn + r) * K + koff + c8 * 8;
            cp16(base + soff, src);
        }
        asm volatile("cp.async.commit_group;" ::: "memory");
    };

    // ---- mma-side addressing: 16 warps, 4x4, warp tile 32x32 ----
    const int wm = wid & 3, wn = wid >> 2;
    const uint32_t xorm = (uint32_t)(lane & 7) << 4;
    const uint32_t rowA = (uint32_t)(wm * 32 + ((lane >> 3) & 1) * 8 + (lane & 7));
    const uint32_t kaddA = (uint32_t)(((lane >> 4) & 1) * 16);
    const uint32_t rowB = (uint32_t)(wn * 32 + ((lane >> 4) & 1) * 8 + (lane & 7));
    const uint32_t kaddB = (uint32_t)(((lane >> 3) & 1) * 16);

    float acc[2][4][4];
#pragma unroll
    for (int i = 0; i < 2; ++i)
#pragma unroll
        for (int j = 0; j < 4; ++j)
#pragma unroll
            for (int e = 0; e < 4; ++e) acc[i][j][e] = 0.f;

    auto MMA_CHUNK = [&](int s) {
        const uint32_t aB = smb + s * STAGE;
        const uint32_t bB = aB + 16384;
#pragma unroll
        for (int ks = 0; ks < 4; ++ks) {
            const uint32_t kb = ks * 32;
            uint32_t ah[2][4], bh[4][2];
#pragma unroll
            for (int i = 0; i < 2; ++i) {
                uint32_t off = (rowA + i * 16) * 128 + ((kb + kaddA) ^ xorm);
                ldsm4(ah[i][0], ah[i][1], ah[i][2], ah[i][3], aB + off);
            }
#pragma unroll
            for (int j2 = 0; j2 < 2; ++j2) {
                uint32_t off = (rowB + j2 * 16) * 128 + ((kb + kaddB) ^ xorm);
                ldsm4(bh[2 * j2][0], bh[2 * j2][1], bh[2 * j2 + 1][0],
                      bh[2 * j2 + 1][1], bB + off);
            }
#pragma unroll
            for (int i = 0; i < 2; ++i)
#pragma unroll
                for (int j = 0; j < 4; ++j)
                    mma_h(acc[i][j], ah[i], bh[j]);
        }
    };

    // ---- 3-stage pipelined main loop ----
    ISSUE(0);
    ISSUE(1);
    for (int c = 0; c < nc; ++c) {
        if (c + 1 < nc)
            asm volatile("cp.async.wait_group 1;" ::: "memory");
        else
            asm volatile("cp.async.wait_group 0;" ::: "memory");
        __syncthreads();
        if (c + 2 < nc) ISSUE(c + 2);
        MMA_CHUNK(c % NSTAGE);
    }

    // ---- epilogue ----
#pragma unroll
    for (int i = 0; i < 2; ++i) {
        const int r0 = bm + wm * 32 + i * 16 + (lane >> 2);
#pragma unroll
        for (int j = 0; j < 4; ++j) {
            const int cc = bn + wn * 32 + j * 8 + (lane & 3) * 2;
            float2 bi = *reinterpret_cast<const float2*>(bias + cc);
            float o0 = acc[i][j][0] + bi.x, o1 = acc[i][j][1] + bi.y;
            float o2 = acc[i][j][2] + bi.x, o3 = acc[i][j][3] + bi.y;
            if (EPI == 1) {
                o0 = 0.5f * o0 * (1.0f + erff(o0 * 0.7071067811865475f));
                o1 = 0.5f * o1 * (1.0f + erff(o1 * 0.7071067811865475f));
                o2 = 0.5f * o2 * (1.0f + erff(o2 * 0.7071067811865475f));
                o3 = 0.5f * o3 * (1.0f + erff(o3 * 0.7071067811865475f));
                *reinterpret_cast<uint32_t*>(Ch + (size_t)r0 * N + cc) = packh(o0, o1);
                *reinterpret_cast<uint32_t*>(Ch + (size_t)(r0 + 8) * N + cc) =
                    packh(o2, o3);
            } else {
                *reinterpret_cast<float2*>(C + (size_t)r0 * N + cc) =
                    make_float2(o0, o1);
                *reinterpret_cast<float2*>(C + (size_t)(r0 + 8) * N + cc) =
                    make_float2(o2, o3);
            }
        }
    }
}

// ---------------- fp32 -> fp16 convert (stream) -------------------------------
__global__ void cvt_h_kernel(const float4* __restrict__ src, uint2* __restrict__ dst,
                             int n4) {
    int i = blockIdx.x * 256 + threadIdx.x;
    if (i < n4) {
        float4 v = src[i];
        uint2 o;
        o.x = packh(v.x, v.y);
        o.y = packh(v.z, v.w);
        dst[i] = o;
    }
}

// ---------------- prep: u_k, u_v, wsum_k, wsum_v ------------------------------
__global__ void prep_kernel(const float* __restrict__ cond_emb,
                            const float* __restrict__ Wk,
                            const float* __restrict__ Wv) {
    __shared__ __align__(16) float s_pad[256];
    int b = blockIdx.x;
    int t = threadIdx.x;
    if (t < 256) {
        int src = (t + 250) % 252;              // (t - 2) mod 252
        s_pad[t] = cond_emb[b * LRAW + src];
    }
    __syncthreads();
    int n = t;
    const float4* wk4 = reinterpret_cast<const float4*>(Wk + (size_t)n * 256);
    const float4* wv4 = reinterpret_cast<const float4*>(Wv + (size_t)n * 256);
    const float4* p4  = reinterpret_cast<const float4*>(s_pad);
    float uk = 0.f, uv = 0.f, sk = 0.f, sv = 0.f;
#pragma unroll 8
    for (int c = 0; c < 64; c++) {
        float4 p = p4[c];
        float4 k = wk4[c];
        float4 v = wv4[c];
        uk += p.x * k.x + p.y * k.y + p.z * k.z + p.w * k.w;
        uv += p.x * v.x + p.y * v.y + p.z * v.z + p.w * v.w;
        sk += k.x + k.y + k.z + k.w;
        sv += v.x + v.y + v.z + v.w;
    }
    g_uk[b * CDIM + n] = uk;
    g_uv[b * CDIM + n] = uv;
    if (b == 0) { g_wsk[n] = sk; g_wsv[n] = sv; }
}

// ---------------- attention (collapsed) + LN1: one warp per token -------------
// Writes query fp32 (residual for LN2) AND fp16 (FFN1 A operand).
__global__ __launch_bounds__(256)
void attn_ln1_kernel(const float* __restrict__ bv,
                     const float* __restrict__ conv_w,
                     const float* __restrict__ conv_b,
                     const float* __restrict__ ln1_w,
                     const float* __restrict__ ln1_b) {
    __shared__ __align__(16) float s_uk[CDIM], s_uv[CDIM], s_wsk[CDIM],
                                   s_wsv[CDIM], s_bv[CDIM], s_lw[CDIM],
                                   s_lb[CDIM], s_cw[SLEN], s_cb[SLEN];
    const int t = threadIdx.x;
    const int token0 = blockIdx.x * 8;
    const int b = token0 >> 10;
    for (int i = t; i < CDIM; i += 256) {
        s_uk[i] = g_uk[b * CDIM + i];
        s_uv[i] = g_uv[b * CDIM + i];
        s_wsk[i] = g_wsk[i];
        s_wsv[i] = g_wsv[i];
        s_bv[i] = bv[i];
        s_lw[i] = ln1_w[i];
        s_lb[i] = ln1_b[i];
    }
    if (t < SLEN) { s_cw[t] = conv_w[t]; s_cb[t] = conv_b[t]; }
    __syncthreads();

    const int warp = t >> 5, lane = t & 31;
    const int token = token0 + warp;
    const float4* qrow = reinterpret_cast<const float4*>(g_q + (size_t)token * CDIM);

    float4 qv[4];
    float A = 0.f, Bk = 0.f;
#pragma unroll
    for (int j = 0; j < 4; j++) {
        int i4 = j * 32 + lane;
        qv[j] = qrow[i4];
        float4 uk = reinterpret_cast<const float4*>(s_uk)[i4];
        float4 wk = reinterpret_cast<const float4*>(s_wsk)[i4];
        A  += qv[j].x * uk.x + qv[j].y * uk.y + qv[j].z * uk.z + qv[j].w * uk.w;
        Bk += qv[j].x * wk.x + qv[j].y * wk.y + qv[j].z * wk.z + qv[j].w * wk.w;
    }
#pragma unroll
    for (int o = 16; o > 0; o >>= 1) {
        A  += __shfl_xor_sync(0xffffffffu, A, o);
        Bk += __shfl_xor_sync(0xffffffffu, Bk, o);
    }

    const float scale = 0.04419417382415922f;   // 1/sqrt(512)
    float l[4], m = -1e30f;
#pragma unroll
    for (int j = 0; j < 4; j++) {
        int s = j * 32 + lane;
        l[j] = scale * (s_cw[s] * A + s_cb[s] * Bk);
        m = fmaxf(m, l[j]);
    }
#pragma unroll
    for (int o = 16; o > 0; o >>= 1)
        m = fmaxf(m, __shfl_xor_sync(0xffffffffu, m, o));

    float Z = 0.f, an = 0.f, bn = 0.f;
#pragma unroll
    for (int j = 0; j < 4; j++) {
        int s = j * 32 + lane;
        float e = expf(l[j] - m);
        Z += e;
        an += e * s_cw[s];
        bn += e * s_cb[s];
    }
#pragma unroll
    for (int o = 16; o > 0; o >>= 1) {
        Z  += __shfl_xor_sync(0xffffffffu, Z, o);
        an += __shfl_xor_sync(0xffffffffu, an, o);
        bn += __shfl_xor_sync(0xffffffffu, bn, o);
    }
    const float alpha = an / Z;
    const float beta  = bn / Z;

    float y[16];
    float sum = 0.f, sq = 0.f;
#pragma unroll
    for (int j = 0; j < 4; j++) {
        int i4 = j * 32 + lane;
        float4 uv = reinterpret_cast<const float4*>(s_uv)[i4];
        float4 wv = reinterpret_cast<const float4*>(s_wsv)[i4];
        float4 bb = reinterpret_cast<const float4*>(s_bv)[i4];
        float y0 = qv[j].x + alpha * uv.x + beta * wv.x + bb.x;
        float y1 = qv[j].y + alpha * uv.y + beta * wv.y + bb.y;
        float y2 = qv[j].z + alpha * uv.z + beta * wv.z + bb.z;
        float y3 = qv[j].w + alpha * uv.w + beta * wv.w + bb.w;
        y[j * 4 + 0] = y0; y[j * 4 + 1] = y1; y[j * 4 + 2] = y2; y[j * 4 + 3] = y3;
        sum += y0 + y1 + y2 + y3;
        sq  += y0 * y0 + y1 * y1 + y2 * y2 + y3 * y3;
    }
#pragma unroll
    for (int o = 16; o > 0; o >>= 1) {
        sum += __shfl_xor_sync(0xffffffffu, sum, o);
        sq  += __shfl_xor_sync(0xffffffffu, sq, o);
    }
    const float mean = sum * (1.f / 512.f);
    const float var  = sq * (1.f / 512.f) - mean * mean;
    const float rstd = rsqrtf(var + LN_EPS);

    float4* orow = reinterpret_cast<float4*>(g_query + (size_t)token * CDIM);
    uint2* hrow = reinterpret_cast<uint2*>(g_qyh + (size_t)token * CDIM);
#pragma unroll
    for (int j = 0; j < 4; j++) {
        int i4 = j * 32 + lane;
        float4 lw = reinterpret_cast<const float4*>(s_lw)[i4];
        float4 lb = reinterpret_cast<const float4*>(s_lb)[i4];
        float4 o;
        o.x = (y[j * 4 + 0] - mean) * rstd * lw.x + lb.x;
        o.y = (y[j * 4 + 1] - mean) * rstd * lw.y + lb.y;
        o.z = (y[j * 4 + 2] - mean) * rstd * lw.z + lb.z;
        o.w = (y[j * 4 + 3] - mean) * rstd * lw.w + lb.w;
        orow[i4] = o;
        uint2 h;
        h.x = packh(o.x, o.y);
        h.y = packh(o.z, o.w);
        hrow[i4] = h;
    }
}

// ---------------- LN2(query + ff) + x: one warp per token ---------------------
__global__ __launch_bounds__(256)
void ln2_add_kernel(const float* __restrict__ x,
                    const float* __restrict__ ln2_w,
                    const float* __restrict__ ln2_b,
                    float* __restrict__ out) {
    const int t = threadIdx.x;
    const int warp = t >> 5, lane = t & 31;
    const int token = blockIdx.x * 8 + warp;
    const float4* qr = reinterpret_cast<const float4*>(g_query + (size_t)token * CDIM);
    const float4* fr = reinterpret_cast<const float4*>(g_ff + (size_t)token * CDIM);
    const float4* xr = reinterpret_cast<const float4*>(x + (size_t)token * CDIM);
    float4* orow = reinterpret_cast<float4*>(out + (size_t)token * CDIM);

    float y[16];
    float4 xs[4];
    float sum = 0.f, sq = 0.f;
#pragma unroll
    for (int j = 0; j < 4; j++) {
        int i4 = j * 32 + lane;
        float4 a = qr[i4];
        float4 f = fr[i4];
        xs[j] = xr[i4];
        float y0 = a.x + f.x, y1 = a.y + f.y, y2 = a.z + f.z, y3 = a.w + f.w;
        y[j * 4 + 0] = y0; y[j * 4 + 1] = y1; y[j * 4 + 2] = y2; y[j * 4 + 3] = y3;
        sum += y0 + y1 + y2 + y3;
        sq  += y0 * y0 + y1 * y1 + y2 * y2 + y3 * y3;
    }
#pragma unroll
    for (int o = 16; o > 0; o >>= 1) {
        sum += __shfl_xor_sync(0xffffffffu, sum, o);
        sq  += __shfl_xor_sync(0xffffffffu, sq, o);
    }
    const float mean = sum * (1.f / 512.f);
    const float var  = sq * (1.f / 512.f) - mean * mean;
    const float rstd = rsqrtf(var + LN_EPS);

#pragma unroll
    for (int j = 0; j < 4; j++) {
        int i4 = j * 32 + lane;
        float4 lw = reinterpret_cast<const float4*>(ln2_w)[i4];
        float4 lb = reinterpret_cast<const float4*>(ln2_b)[i4];
        float4 o;
        o.x = (y[j * 4 + 0] - mean) * rstd * lw.x + lb.x + xs[j].x;
        o.y = (y[j * 4 + 1] - mean) * rstd * lw.y + lb.y + xs[j].y;
        o.z = (y[j * 4 + 2] - mean) * rstd * lw.z + lb.z + xs[j].z;
        o.w = (y[j * 4 + 3] - mean) * rstd * lw.w + lb.w + xs[j].w;
        orow[i4] = o;
    }
}

// ---------------- launch ------------------------------------------------------
extern "C" void kernel_launch(void* const* d_in, const int* in_sizes, int n_in,
                              void* d_out, int out_size) {
    const float* x        = (const float*)d_in[0];
    const float* cond_emb = (const float*)d_in[1];
    const float* Wq       = (const float*)d_in[2];
    const float* bq       = (const float*)d_in[3];
    const float* Wk       = (const float*)d_in[4];
    // d_in[5] = bk: constant shift along s, cancels in softmax
    const float* Wv       = (const float*)d_in[6];
    const float* bv       = (const float*)d_in[7];
    const float* conv_w   = (const float*)d_in[8];
    const float* conv_b   = (const float*)d_in[9];
    const float* ln1_w    = (const float*)d_in[10];
    const float* ln1_b    = (const float*)d_in[11];
    const float* W1       = (const float*)d_in[12];
    const float* b1       = (const float*)d_in[13];
    const float* W2       = (const float*)d_in[14];
    const float* b2       = (const float*)d_in[15];
    const float* ln2_w    = (const float*)d_in[16];
    const float* ln2_b    = (const float*)d_in[17];
    float* out            = (float*)d_out;

    float *pq, *pff;
    cudaGetSymbolAddress((void**)&pq, g_q);
    cudaGetSymbolAddress((void**)&pff, g_ff);
    uint16_t *pxh, *pqyh, *phh, *pwqh, *pw1h, *pw2h;
    cudaGetSymbolAddress((void**)&pxh, g_xh);
    cudaGetSymbolAddress((void**)&pqyh, g_qyh);
    cudaGetSymbolAddress((void**)&phh, g_hh);
    cudaGetSymbolAddress((void**)&pwqh, g_wqh);
    cudaGetSymbolAddress((void**)&pw1h, g_w1h);
    cudaGetSymbolAddress((void**)&pw2h, g_w2h);

    cudaFuncSetAttribute(gemm_h<0>, cudaFuncAttributeMaxDynamicSharedMemorySize,
                         GT_SMEM);
    cudaFuncSetAttribute(gemm_h<1>, cudaFuncAttributeMaxDynamicSharedMemorySize,
                         GT_SMEM);

    // 0) operand prep (fp32 -> fp16)
    cvt_h_kernel<<<(MTOK * CDIM / 4 + 255) / 256, 256>>>(
        (const float4*)x, (uint2*)pxh, MTOK * CDIM / 4);
    cvt_h_kernel<<<(CDIM * CDIM / 4 + 255) / 256, 256>>>(
        (const float4*)Wq, (uint2*)pwqh, CDIM * CDIM / 4);
    cvt_h_kernel<<<(2 * CDIM * CDIM / 4 + 255) / 256, 256>>>(
        (const float4*)W1, (uint2*)pw1h, 2 * CDIM * CDIM / 4);
    cvt_h_kernel<<<(2 * CDIM * CDIM / 4 + 255) / 256, 256>>>(
        (const float4*)W2, (uint2*)pw2h, 2 * CDIM * CDIM / 4);

    // 1) conditioner factorization
    prep_kernel<<<BATCH, 512>>>(cond_emb, Wk, Wv);

    // 2) q = x @ Wq^T + bq   (fp16, fp32 accum)
    gemm_h<0><<<dim3(CDIM / 128, MTOK / 128), 512, GT_SMEM>>>(
        pxh, pwqh, bq, pq, nullptr, CDIM, CDIM);

    // 3) collapsed attention + LN1 -> query (fp32 + fp16)
    attn_ln1_kernel<<<MTOK / 8, 256>>>(bv, conv_w, conv_b, ln1_w, ln1_b);

    // 4) h = gelu(query @ W1^T + b1) -> fp16
    gemm_h<1><<<dim3((2 * CDIM) / 128, MTOK / 128), 512, GT_SMEM>>>(
        pqyh, pw1h, b1, nullptr, phh, 2 * CDIM, CDIM);

    // 5) ff = h @ W2^T + b2
    gemm_h<0><<<dim3(CDIM / 128, MTOK / 128), 512, GT_SMEM>>>(
        phh, pw2h, b2, pff, nullptr, CDIM, 2 * CDIM);

    // 6) out = LN2(query + ff) + x
    ln2_add_kernel<<<MTOK / 8, 256>>>(x, ln2_w, ln2_b, out);
}

// round 15
// speedup vs baseline: 4.8452x; 1.0118x over previous
#include <cuda_runtime.h>
#include <cuda_bf16.h>
#include <cuda_fp16.h>
#include <math.h>
#include <stdint.h>

// Problem constants
#define BATCH 32
#define SEQT  1024
#define CDIM  512
#define LRAW  252
#define SLEN  128
#define MTOK  (BATCH * SEQT)   // 32768
#define LN_EPS 1e-5f

// ---------------- scratch (device globals; no allocation allowed) -------------
__device__ float g_query[MTOK * CDIM];        // LN1(q + attn_out) fp32 (residual)
__device__ float g_uk[BATCH * CDIM];
__device__ float g_uv[BATCH * CDIM];
__device__ float g_wsk[CDIM];
__device__ float g_wsv[CDIM];

// fp16 operands
__device__ uint16_t g_xh[MTOK * CDIM];            // x fp16
__device__ uint16_t g_qyh[MTOK * CDIM];           // query fp16
__device__ uint16_t g_hh[MTOK * 2 * CDIM];        // gelu out fp16
__device__ uint16_t g_wqh[CDIM * CDIM];           // Wq fp16
__device__ uint16_t g_w1h[2 * CDIM * CDIM];       // W1 fp16
__device__ uint16_t g_w2h[CDIM * 2 * CDIM];       // W2 fp16

// =============================================================================
// helpers
// =============================================================================
__device__ __forceinline__ uint32_t smem_u32(const void* p) {
    uint32_t a;
    asm("{ .reg .u64 t; cvta.to.shared.u64 t, %1; cvt.u32.u64 %0, t; }"
        : "=r"(a) : "l"(p));
    return a;
}

__device__ __forceinline__ uint32_t packh(float a, float b) {
    return (uint32_t)__half_as_ushort(__float2half(a)) |
           ((uint32_t)__half_as_ushort(__float2half(b)) << 16);
}

__device__ __forceinline__ void ldsm4(uint32_t& r0, uint32_t& r1, uint32_t& r2,
                                      uint32_t& r3, uint32_t addr) {
    asm volatile("ldmatrix.sync.aligned.m8n8.x4.shared.b16 {%0,%1,%2,%3}, [%4];"
                 : "=r"(r0), "=r"(r1), "=r"(r2), "=r"(r3) : "r"(addr));
}

__device__ __forceinline__ void mma_h(float* d, const uint32_t* a,
                                      const uint32_t* b) {
    asm volatile(
        "mma.sync.aligned.m16n8k16.row.col.f32.f16.f16.f32 "
        "{%0,%1,%2,%3}, {%4,%5,%6,%7}, {%8,%9}, {%0,%1,%2,%3};"
        : "+f"(d[0]), "+f"(d[1]), "+f"(d[2]), "+f"(d[3])
        : "r"(a[0]), "r"(a[1]), "r"(a[2]), "r"(a[3]), "r"(b[0]), "r"(b[1]));
}

__device__ __forceinline__ void cp16(uint32_t dst, const void* src) {
    asm volatile("cp.async.cg.shared.global [%0], [%1], 16;"
                 :: "r"(dst), "l"(src));
}

// =============================================================================
// FFN1 GEMM (unchanged structure): C = A*B^T + bias, GELU, fp16 out
// CTA 128x128, K-chunk 64, 3-stage cp.async, 512 thr, warp tile 32x32.
// =============================================================================
#define NSTAGE 3
#define STAGE 32768u
#define GT_SMEM (NSTAGE * STAGE)

__global__ void __launch_bounds__(512, 1)
gemm_h_gelu(const uint16_t* __restrict__ Ah, const uint16_t* __restrict__ Bh,
            const float* __restrict__ bias, uint16_t* __restrict__ Ch,
            int N, int K) {
    extern __shared__ __align__(1024) char sm[];
    const uint32_t smb = smem_u32(sm);
    const int tid = threadIdx.x;
    const int wid = tid >> 5, lane = tid & 31;
    const int bn = blockIdx.x * 128;
    const int bm = blockIdx.y * 128;
    const int nc = K >> 6;

    auto ISSUE = [&](int c) {
        const uint32_t base = smb + (c % NSTAGE) * STAGE;
        const int koff = c * 64;
#pragma unroll
        for (int i = 0; i < 4; ++i) {
            const int q = tid + 512 * i;
            const int mat = q >> 10;
            const int w = q & 1023;
            const int r = w >> 3;
            const int c8 = w & 7;
            const uint32_t soff = (uint32_t)mat * 16384u + (uint32_t)r * 128u +
                (((uint32_t)c8 * 16u) ^ (((uint32_t)r & 7u) << 4));
            const uint16_t* src = mat == 0
                ? Ah + (size_t)(bm + r) * K + koff + c8 * 8
                : Bh + (size_t)(bn + r) * K + koff + c8 * 8;
            cp16(base + soff, src);
        }
        asm volatile("cp.async.commit_group;" ::: "memory");
    };

    const int wm = wid & 3, wn = wid >> 2;
    const uint32_t xorm = (uint32_t)(lane & 7) << 4;
    const uint32_t rowA = (uint32_t)(wm * 32 + ((lane >> 3) & 1) * 8 + (lane & 7));
    const uint32_t kaddA = (uint32_t)(((lane >> 4) & 1) * 16);
    const uint32_t rowB = (uint32_t)(wn * 32 + ((lane >> 4) & 1) * 8 + (lane & 7));
    const uint32_t kaddB = (uint32_t)(((lane >> 3) & 1) * 16);

    float acc[2][4][4];
#pragma unroll
    for (int i = 0; i < 2; ++i)
#pragma unroll
        for (int j = 0; j < 4; ++j)
#pragma unroll
            for (int e = 0; e < 4; ++e) acc[i][j][e] = 0.f;

    auto MMA_CHUNK = [&](int s) {
        const uint32_t aB = smb + s * STAGE;
        const uint32_t bB = aB + 16384;
#pragma unroll
        for (int ks = 0; ks < 4; ++ks) {
            const uint32_t kb = ks * 32;
            uint32_t ah[2][4], bh[4][2];
#pragma unroll
            for (int i = 0; i < 2; ++i) {
                uint32_t off = (rowA + i * 16) * 128 + ((kb + kaddA) ^ xorm);
                ldsm4(ah[i][0], ah[i][1], ah[i][2], ah[i][3], aB + off);
            }
#pragma unroll
            for (int j2 = 0; j2 < 2; ++j2) {
                uint32_t off = (rowB + j2 * 16) * 128 + ((kb + kaddB) ^ xorm);
                ldsm4(bh[2 * j2][0], bh[2 * j2][1], bh[2 * j2 + 1][0],
                      bh[2 * j2 + 1][1], bB + off);
            }
#pragma unroll
            for (int i = 0; i < 2; ++i)
#pragma unroll
                for (int j = 0; j < 4; ++j)
                    mma_h(acc[i][j], ah[i], bh[j]);
        }
    };

    ISSUE(0);
    ISSUE(1);
    for (int c = 0; c < nc; ++c) {
        if (c + 1 < nc)
            asm volatile("cp.async.wait_group 1;" ::: "memory");
        else
            asm volatile("cp.async.wait_group 0;" ::: "memory");
        __syncthreads();
        if (c + 2 < nc) ISSUE(c + 2);
        MMA_CHUNK(c % NSTAGE);
    }

#pragma unroll
    for (int i = 0; i < 2; ++i) {
        const int r0 = bm + wm * 32 + i * 16 + (lane >> 2);
#pragma unroll
        for (int j = 0; j < 4; ++j) {
            const int cc = bn + wn * 32 + j * 8 + (lane & 3) * 2;
            float2 bi = *reinterpret_cast<const float2*>(bias + cc);
            float o0 = acc[i][j][0] + bi.x, o1 = acc[i][j][1] + bi.y;
            float o2 = acc[i][j][2] + bi.x, o3 = acc[i][j][3] + bi.y;
            o0 = 0.5f * o0 * (1.0f + erff(o0 * 0.7071067811865475f));
            o1 = 0.5f * o1 * (1.0f + erff(o1 * 0.7071067811865475f));
            o2 = 0.5f * o2 * (1.0f + erff(o2 * 0.7071067811865475f));
            o3 = 0.5f * o3 * (1.0f + erff(o3 * 0.7071067811865475f));
            *reinterpret_cast<uint32_t*>(Ch + (size_t)r0 * N + cc) = packh(o0, o1);
            *reinterpret_cast<uint32_t*>(Ch + (size_t)(r0 + 8) * N + cc) =
                packh(o2, o3);
        }
    }
}

// =============================================================================
// Fused full-row GEMM: CTA tile 64 x 512 (full N), 16 warps (2m x 8n),
// warp tile 32x64, K-chunk 64, 3-stage cp.async (72KB/stage).
// MODE 0: q = A*Wq^T + bq, then collapsed attention + LN1 -> query fp32 + fp16
// MODE 1: ff = A*W2^T + b2, then LN2(query + ff) + x -> out
// =============================================================================
#define FSTAGE 73728u             // A 8KB | B 64KB
#define FNST 3
#define F_SMEM (FNST * FSTAGE)    // 216KB

template <int MODE>
__global__ void __launch_bounds__(512, 1)
gemm_fused(const uint16_t* __restrict__ Ah, const uint16_t* __restrict__ Bh,
           const float* __restrict__ bias, int K,
           const float* __restrict__ bv, const float* __restrict__ conv_w,
           const float* __restrict__ conv_b, const float* __restrict__ ln1_w,
           const float* __restrict__ ln1_b, float* __restrict__ queryOut,
           uint16_t* __restrict__ qyhOut,
           const float* __restrict__ query, const float* __restrict__ xin,
           const float* __restrict__ ln2_w, const float* __restrict__ ln2_b,
           float* __restrict__ out) {
    extern __shared__ __align__(1024) char sm[];
    const uint32_t smb = smem_u32(sm);
    const int tid = threadIdx.x;
    const int wid = tid >> 5, lane = tid & 31;
    const int bm = blockIdx.x * 64;
    const int nc = K >> 6;

    // ---- cp.async loader: A 512 chunks (1/thread), B 4096 chunks (8/thread) --
    auto ISSUE = [&](int c) {
        const uint32_t base = smb + (c % FNST) * FSTAGE;
        const int koff = c * 64;
        {
            const int r = tid >> 3, c8 = tid & 7;
            const uint32_t soff = (uint32_t)r * 128u +
                (((uint32_t)c8 * 16u) ^ (((uint32_t)r & 7u) << 4));
            cp16(base + soff, Ah + (size_t)(bm + r) * K + koff + c8 * 8);
        }
#pragma unroll
        for (int i = 0; i < 8; ++i) {
            const int q = tid + 512 * i;
            const int r = q >> 3, c8 = q & 7;
            const uint32_t soff = 8192u + (uint32_t)r * 128u +
                (((uint32_t)c8 * 16u) ^ (((uint32_t)r & 7u) << 4));
            cp16(base + soff, Bh + (size_t)r * K + koff + c8 * 8);
        }
        asm volatile("cp.async.commit_group;" ::: "memory");
    };

    // ---- mma addressing: wm in {0,1} (rows), wn in 0..7 (64-col groups) ----
    const int wm = wid & 1, wn = wid >> 1;
    const uint32_t xorm = (uint32_t)(lane & 7) << 4;
    const uint32_t rowA = (uint32_t)(wm * 32 + ((lane >> 3) & 1) * 8 + (lane & 7));
    const uint32_t kaddA = (uint32_t)(((lane >> 4) & 1) * 16);
    const uint32_t rowB = (uint32_t)(wn * 64 + ((lane >> 4) & 1) * 8 + (lane & 7));
    const uint32_t kaddB = (uint32_t)(((lane >> 3) & 1) * 16);

    float acc[2][8][4];
#pragma unroll
    for (int i = 0; i < 2; ++i)
#pragma unroll
        for (int j = 0; j < 8; ++j)
#pragma unroll
            for (int e = 0; e < 4; ++e) acc[i][j][e] = 0.f;

    auto MMA_CHUNK = [&](int s) {
        const uint32_t aB = smb + s * FSTAGE;
        const uint32_t bB = aB + 8192;
#pragma unroll
        for (int ks = 0; ks < 4; ++ks) {
            const uint32_t kb = ks * 32;
            uint32_t ah[2][4], bh[8][2];
#pragma unroll
            for (int i = 0; i < 2; ++i) {
                uint32_t off = (rowA + i * 16) * 128 + ((kb + kaddA) ^ xorm);
                ldsm4(ah[i][0], ah[i][1], ah[i][2], ah[i][3], aB + off);
            }
#pragma unroll
            for (int j2 = 0; j2 < 4; ++j2) {
                uint32_t off = (rowB + j2 * 16) * 128 + ((kb + kaddB) ^ xorm);
                ldsm4(bh[2 * j2][0], bh[2 * j2][1], bh[2 * j2 + 1][0],
                      bh[2 * j2 + 1][1], bB + off);
            }
#pragma unroll
            for (int i = 0; i < 2; ++i)
#pragma unroll
                for (int j = 0; j < 8; ++j)
                    mma_h(acc[i][j], ah[i], bh[j]);
        }
    };

    ISSUE(0);
    ISSUE(1);
    for (int c = 0; c < nc; ++c) {
        if (c + 1 < nc)
            asm volatile("cp.async.wait_group 1;" ::: "memory");
        else
            asm volatile("cp.async.wait_group 0;" ::: "memory");
        __syncthreads();
        if (c + 2 < nc) ISSUE(c + 2);
        MMA_CHUNK(c % FNST);
    }
    __syncthreads();   // MMA done; smem now reusable by the epilogue

    // ---- epilogue smem layout (overlaid on stage memory) ----
    float* p = reinterpret_cast<float*>(sm);
    // arrays of 512 floats each
    float* e_bias = p;            // bias (bq or b2)
    float* e_c1   = p + 512;      // MODE0: uk   | MODE1: ln2_w
    float* e_c2   = p + 1024;     // MODE0: wsk  | MODE1: ln2_b
    float* e_c3   = p + 1536;     // MODE0: uv
    float* e_c4   = p + 2048;     // MODE0: wsv
    float* e_c5   = p + 2560;     // MODE0: bv
    float* e_c6   = p + 3072;     // MODE0: ln1_w
    float* e_c7   = p + 3584;     // MODE0: ln1_b
    float* e_cw   = p + 4096;     // 128
    float* e_cb   = p + 4224;     // 128
    float* redA   = p + 4352;     // 64 x 8
    float* redB   = p + 4864;     // 64 x 8
    float* s_al   = p + 5376;     // 64 (alpha | mean)
    float* s_be   = p + 5440;     // 64 (beta  | rstd)
    float* s_mean = p + 5504;     // 64
    float* s_rstd = p + 5568;     // 64

    const int batch = bm >> 10;
    e_bias[tid & 511] = bias[tid & 511];
    if (MODE == 0) {
        e_c1[tid & 511] = g_uk[batch * CDIM + (tid & 511)];
        e_c2[tid & 511] = g_wsk[tid & 511];
        e_c3[tid & 511] = g_uv[batch * CDIM + (tid & 511)];
        e_c4[tid & 511] = g_wsv[tid & 511];
        e_c5[tid & 511] = bv[tid & 511];
        e_c6[tid & 511] = ln1_w[tid & 511];
        e_c7[tid & 511] = ln1_b[tid & 511];
        if (tid < SLEN) { e_cw[tid] = conv_w[tid]; e_cb[tid] = conv_b[tid]; }
    } else {
        e_c1[tid & 511] = ln2_w[tid & 511];
        e_c2[tid & 511] = ln2_b[tid & 511];
    }
    __syncthreads();

    // local rows handled by this thread: k=0..3 -> wm*32 + (k>>1)*16 + (lane>>2) + (k&1)*8
    int rl[4];
#pragma unroll
    for (int k = 0; k < 4; ++k)
        rl[k] = wm * 32 + (k >> 1) * 16 + (lane >> 2) + (k & 1) * 8;

    if (MODE == 0) {
        // ---- phase 1: q = acc + bq; partial dots q.uk, q.wsk ----
        float pA[4] = {0, 0, 0, 0}, pB[4] = {0, 0, 0, 0};
#pragma unroll
        for (int i = 0; i < 2; ++i)
#pragma unroll
            for (int j = 0; j < 8; ++j) {
                const int c0 = wn * 64 + j * 8 + (lane & 3) * 2;
                const float b0 = e_bias[c0], b1 = e_bias[c0 + 1];
                acc[i][j][0] += b0; acc[i][j][1] += b1;
                acc[i][j][2] += b0; acc[i][j][3] += b1;
                const float u0 = e_c1[c0], u1 = e_c1[c0 + 1];
                const float w0 = e_c2[c0], w1 = e_c2[c0 + 1];
                pA[2 * i]     += acc[i][j][0] * u0 + acc[i][j][1] * u1;
                pB[2 * i]     += acc[i][j][0] * w0 + acc[i][j][1] * w1;
                pA[2 * i + 1] += acc[i][j][2] * u0 + acc[i][j][3] * u1;
                pB[2 * i + 1] += acc[i][j][2] * w0 + acc[i][j][3] * w1;
            }
#pragma unroll
        for (int o = 1; o <= 2; o <<= 1)
#pragma unroll
            for (int k = 0; k < 4; ++k) {
                pA[k] += __shfl_xor_sync(0xffffffffu, pA[k], o);
                pB[k] += __shfl_xor_sync(0xffffffffu, pB[k], o);
            }
        if ((lane & 3) == 0)
#pragma unroll
            for (int k = 0; k < 4; ++k) {
                redA[rl[k] * 8 + wn] = pA[k];
                redB[rl[k] * 8 + wn] = pB[k];
            }
        __syncthreads();

        // ---- phase 2: per-row softmax over S=128 (1 thread / row) ----
        if (tid < 64) {
            float A = 0.f, Bd = 0.f;
#pragma unroll
            for (int w = 0; w < 8; ++w) {
                A  += redA[tid * 8 + w];
                Bd += redB[tid * 8 + w];
            }
            const float scale = 0.04419417382415922f;   // 1/sqrt(512)
            float m = -1e30f;
            for (int s = 0; s < SLEN; ++s) {
                float l = scale * (e_cw[s] * A + e_cb[s] * Bd);
                m = fmaxf(m, l);
            }
            float Z = 0.f, an = 0.f, bn = 0.f;
            for (int s = 0; s < SLEN; ++s) {
                float l = scale * (e_cw[s] * A + e_cb[s] * Bd);
                float e = expf(l - m);
                Z += e; an += e * e_cw[s]; bn += e * e_cb[s];
            }
            s_al[tid] = an / Z;
            s_be[tid] = bn / Z;
        }
        __syncthreads();

        // ---- phase 3: y = q + alpha*uv + beta*wsv + bv; LN1 partials ----
        float pS[4] = {0, 0, 0, 0}, pQ[4] = {0, 0, 0, 0};
        float al[4], be[4];
#pragma unroll
        for (int k = 0; k < 4; ++k) { al[k] = s_al[rl[k]]; be[k] = s_be[rl[k]]; }
#pragma unroll
        for (int i = 0; i < 2; ++i)
#pragma unroll
            for (int j = 0; j < 8; ++j) {
                const int c0 = wn * 64 + j * 8 + (lane & 3) * 2;
                const float uv0 = e_c3[c0], uv1 = e_c3[c0 + 1];
                const float wv0 = e_c4[c0], wv1 = e_c4[c0 + 1];
                const float bb0 = e_c5[c0], bb1 = e_c5[c0 + 1];
                float y0 = acc[i][j][0] + al[2 * i] * uv0 + be[2 * i] * wv0 + bb0;
                float y1 = acc[i][j][1] + al[2 * i] * uv1 + be[2 * i] * wv1 + bb1;
                float y2 = acc[i][j][2] + al[2 * i + 1] * uv0 + be[2 * i + 1] * wv0 + bb0;
                float y3 = acc[i][j][3] + al[2 * i + 1] * uv1 + be[2 * i + 1] * wv1 + bb1;
                acc[i][j][0] = y0; acc[i][j][1] = y1;
                acc[i][j][2] = y2; acc[i][j][3] = y3;
                pS[2 * i]     += y0 + y1;  pQ[2 * i]     += y0 * y0 + y1 * y1;
                pS[2 * i + 1] += y2 + y3;  pQ[2 * i + 1] += y2 * y2 + y3 * y3;
            }
#pragma unroll
        for (int o = 1; o <= 2; o <<= 1)
#pragma unroll
            for (int k = 0; k < 4; ++k) {
                pS[k] += __shfl_xor_sync(0xffffffffu, pS[k], o);
                pQ[k] += __shfl_xor_sync(0xffffffffu, pQ[k], o);
            }
        if ((lane & 3) == 0)
#pragma unroll
            for (int k = 0; k < 4; ++k) {
                redA[rl[k] * 8 + wn] = pS[k];
                redB[rl[k] * 8 + wn] = pQ[k];
            }
        __syncthreads();
        if (tid < 64) {
            float s = 0.f, q2 = 0.f;
#pragma unroll
            for (int w = 0; w < 8; ++w) { s += redA[tid * 8 + w]; q2 += redB[tid * 8 + w]; }
            const float mean = s * (1.f / 512.f);
            const float var  = q2 * (1.f / 512.f) - mean * mean;
            s_mean[tid] = mean;
            s_rstd[tid] = rsqrtf(var + LN_EPS);
        }
        __syncthreads();

        // ---- phase 4: write query fp32 + fp16 ----
        float mn[4], rs[4];
#pragma unroll
        for (int k = 0; k < 4; ++k) { mn[k] = s_mean[rl[k]]; rs[k] = s_rstd[rl[k]]; }
#pragma unroll
        for (int i = 0; i < 2; ++i)
#pragma unroll
            for (int j = 0; j < 8; ++j) {
                const int c0 = wn * 64 + j * 8 + (lane & 3) * 2;
                const float lw0 = e_c6[c0], lw1 = e_c6[c0 + 1];
                const float lb0 = e_c7[c0], lb1 = e_c7[c0 + 1];
                const int g0 = bm + rl[2 * i], g1 = bm + rl[2 * i + 1];
                float o0 = (acc[i][j][0] - mn[2 * i]) * rs[2 * i] * lw0 + lb0;
                float o1 = (acc[i][j][1] - mn[2 * i]) * rs[2 * i] * lw1 + lb1;
                float o2 = (acc[i][j][2] - mn[2 * i + 1]) * rs[2 * i + 1] * lw0 + lb0;
                float o3 = (acc[i][j][3] - mn[2 * i + 1]) * rs[2 * i + 1] * lw1 + lb1;
                *reinterpret_cast<float2*>(queryOut + (size_t)g0 * CDIM + c0) =
                    make_float2(o0, o1);
                *reinterpret_cast<float2*>(queryOut + (size_t)g1 * CDIM + c0) =
                    make_float2(o2, o3);
                *reinterpret_cast<uint32_t*>(qyhOut + (size_t)g0 * CDIM + c0) =
                    packh(o0, o1);
                *reinterpret_cast<uint32_t*>(qyhOut + (size_t)g1 * CDIM + c0) =
                    packh(o2, o3);
            }
    } else {
        // ---- MODE 1: ff = acc + b2; y = query + ff; LN2; + x -> out ----
        float pS[4] = {0, 0, 0, 0}, pQ[4] = {0, 0, 0, 0};
#pragma unroll
        for (int i = 0; i < 2; ++i)
#pragma unroll
            for (int j = 0; j < 8; ++j) {
                const int c0 = wn * 64 + j * 8 + (lane & 3) * 2;
                const float b0 = e_bias[c0], b1 = e_bias[c0 + 1];
                const int g0 = bm + rl[2 * i], g1 = bm + rl[2 * i + 1];
                float2 q0 = *reinterpret_cast<const float2*>(
                    query + (size_t)g0 * CDIM + c0);
                float2 q1 = *reinterpret_cast<const float2*>(
                    query + (size_t)g1 * CDIM + c0);
                float y0 = acc[i][j][0] + b0 + q0.x;
                float y1 = acc[i][j][1] + b1 + q0.y;
                float y2 = acc[i][j][2] + b0 + q1.x;
                float y3 = acc[i][j][3] + b1 + q1.y;
                acc[i][j][0] = y0; acc[i][j][1] = y1;
                acc[i][j][2] = y2; acc[i][j][3] = y3;
                pS[2 * i]     += y0 + y1;  pQ[2 * i]     += y0 * y0 + y1 * y1;
                pS[2 * i + 1] += y2 + y3;  pQ[2 * i + 1] += y2 * y2 + y3 * y3;
            }
#pragma unroll
        for (int o = 1; o <= 2; o <<= 1)
#pragma unroll
            for (int k = 0; k < 4; ++k) {
                pS[k] += __shfl_xor_sync(0xffffffffu, pS[k], o);
                pQ[k] += __shfl_xor_sync(0xffffffffu, pQ[k], o);
            }
        if ((lane & 3) == 0)
#pragma unroll
            for (int k = 0; k < 4; ++k) {
                redA[rl[k] * 8 + wn] = pS[k];
                redB[rl[k] * 8 + wn] = pQ[k];
            }
        __syncthreads();
        if (tid < 64) {
            float s = 0.f, q2 = 0.f;
#pragma unroll
            for (int w = 0; w < 8; ++w) { s += redA[tid * 8 + w]; q2 += redB[tid * 8 + w]; }
            const float mean = s * (1.f / 512.f);
            const float var  = q2 * (1.f / 512.f) - mean * mean;
            s_mean[tid] = mean;
            s_rstd[tid] = rsqrtf(var + LN_EPS);
        }
        __syncthreads();

        float mn[4], rs[4];
#pragma unroll
        for (int k = 0; k < 4; ++k) { mn[k] = s_mean[rl[k]]; rs[k] = s_rstd[rl[k]]; }
#pragma unroll
        for (int i = 0; i < 2; ++i)
#pragma unroll
            for (int j = 0; j < 8; ++j) {
                const int c0 = wn * 64 + j * 8 + (lane & 3) * 2;
                const float lw0 = e_c1[c0], lw1 = e_c1[c0 + 1];
                const float lb0 = e_c2[c0], lb1 = e_c2[c0 + 1];
                const int g0 = bm + rl[2 * i], g1 = bm + rl[2 * i + 1];
                float2 x0 = *reinterpret_cast<const float2*>(
                    xin + (size_t)g0 * CDIM + c0);
                float2 x1 = *reinterpret_cast<const float2*>(
                    xin + (size_t)g1 * CDIM + c0);
                float o0 = (acc[i][j][0] - mn[2 * i]) * rs[2 * i] * lw0 + lb0 + x0.x;
                float o1 = (acc[i][j][1] - mn[2 * i]) * rs[2 * i] * lw1 + lb1 + x0.y;
                float o2 = (acc[i][j][2] - mn[2 * i + 1]) * rs[2 * i + 1] * lw0 + lb0 + x1.x;
                float o3 = (acc[i][j][3] - mn[2 * i + 1]) * rs[2 * i + 1] * lw1 + lb1 + x1.y;
                *reinterpret_cast<float2*>(out + (size_t)g0 * CDIM + c0) =
                    make_float2(o0, o1);
                *reinterpret_cast<float2*>(out + (size_t)g1 * CDIM + c0) =
                    make_float2(o2, o3);
            }
    }
}

// ---------------- fp32 -> fp16 convert (stream) -------------------------------
__global__ void cvt_h_kernel(const float4* __restrict__ src, uint2* __restrict__ dst,
                             int n4) {
    int i = blockIdx.x * 256 + threadIdx.x;
    if (i < n4) {
        float4 v = src[i];
        uint2 o;
        o.x = packh(v.x, v.y);
        o.y = packh(v.z, v.w);
        dst[i] = o;
    }
}

// ---------------- prep: u_k, u_v, wsum_k, wsum_v ------------------------------
__global__ void prep_kernel(const float* __restrict__ cond_emb,
                            const float* __restrict__ Wk,
                            const float* __restrict__ Wv) {
    __shared__ __align__(16) float s_pad[256];
    int b = blockIdx.x;
    int t = threadIdx.x;
    if (t < 256) {
        int src = (t + 250) % 252;              // (t - 2) mod 252
        s_pad[t] = cond_emb[b * LRAW + src];
    }
    __syncthreads();
    int n = t;
    const float4* wk4 = reinterpret_cast<const float4*>(Wk + (size_t)n * 256);
    const float4* wv4 = reinterpret_cast<const float4*>(Wv + (size_t)n * 256);
    const float4* p4  = reinterpret_cast<const float4*>(s_pad);
    float uk = 0.f, uv = 0.f, sk = 0.f, sv = 0.f;
#pragma unroll 8
    for (int c = 0; c < 64; c++) {
        float4 p = p4[c];
        float4 k = wk4[c];
        float4 v = wv4[c];
        uk += p.x * k.x + p.y * k.y + p.z * k.z + p.w * k.w;
        uv += p.x * v.x + p.y * v.y + p.z * v.z + p.w * v.w;
        sk += k.x + k.y + k.z + k.w;
        sv += v.x + v.y + v.z + v.w;
    }
    g_uk[b * CDIM + n] = uk;
    g_uv[b * CDIM + n] = uv;
    if (b == 0) { g_wsk[n] = sk; g_wsv[n] = sv; }
}

// ---------------- launch ------------------------------------------------------
extern "C" void kernel_launch(void* const* d_in, const int* in_sizes, int n_in,
                              void* d_out, int out_size) {
    const float* x        = (const float*)d_in[0];
    const float* cond_emb = (const float*)d_in[1];
    const float* Wq       = (const float*)d_in[2];
    const float* bq       = (const float*)d_in[3];
    const float* Wk       = (const float*)d_in[4];
    // d_in[5] = bk: constant shift along s, cancels in softmax
    const float* Wv       = (const float*)d_in[6];
    const float* bv       = (const float*)d_in[7];
    const float* conv_w   = (const float*)d_in[8];
    const float* conv_b   = (const float*)d_in[9];
    const float* ln1_w    = (const float*)d_in[10];
    const float* ln1_b    = (const float*)d_in[11];
    const float* W1       = (const float*)d_in[12];
    const float* b1       = (const float*)d_in[13];
    const float* W2       = (const float*)d_in[14];
    const float* b2       = (const float*)d_in[15];
    const float* ln2_w    = (const float*)d_in[16];
    const float* ln2_b    = (const float*)d_in[17];
    float* out            = (float*)d_out;

    float* pquery;
    cudaGetSymbolAddress((void**)&pquery, g_query);
    uint16_t *pxh, *pqyh, *phh, *pwqh, *pw1h, *pw2h;
    cudaGetSymbolAddress((void**)&pxh, g_xh);
    cudaGetSymbolAddress((void**)&pqyh, g_qyh);
    cudaGetSymbolAddress((void**)&phh, g_hh);
    cudaGetSymbolAddress((void**)&pwqh, g_wqh);
    cudaGetSymbolAddress((void**)&pw1h, g_w1h);
    cudaGetSymbolAddress((void**)&pw2h, g_w2h);

    cudaFuncSetAttribute(gemm_h_gelu, cudaFuncAttributeMaxDynamicSharedMemorySize,
                         GT_SMEM);
    cudaFuncSetAttribute(gemm_fused<0>,
                         cudaFuncAttributeMaxDynamicSharedMemorySize, F_SMEM);
    cudaFuncSetAttribute(gemm_fused<1>,
                         cudaFuncAttributeMaxDynamicSharedMemorySize, F_SMEM);

    // 0) operand prep (fp32 -> fp16)
    cvt_h_kernel<<<(MTOK * CDIM / 4 + 255) / 256, 256>>>(
        (const float4*)x, (uint2*)pxh, MTOK * CDIM / 4);
    cvt_h_kernel<<<(CDIM * CDIM / 4 + 255) / 256, 256>>>(
        (const float4*)Wq, (uint2*)pwqh, CDIM * CDIM / 4);
    cvt_h_kernel<<<(2 * CDIM * CDIM / 4 + 255) / 256, 256>>>(
        (const float4*)W1, (uint2*)pw1h, 2 * CDIM * CDIM / 4);
    cvt_h_kernel<<<(2 * CDIM * CDIM / 4 + 255) / 256, 256>>>(
        (const float4*)W2, (uint2*)pw2h, 2 * CDIM * CDIM / 4);

    // 1) conditioner factorization
    prep_kernel<<<BATCH, 512>>>(cond_emb, Wk, Wv);

    // 2) fused: q GEMM + collapsed attention + LN1 -> query (fp32 + fp16)
    gemm_fused<0><<<MTOK / 64, 512, F_SMEM>>>(
        pxh, pwqh, bq, CDIM,
        bv, conv_w, conv_b, ln1_w, ln1_b, pquery, pqyh,
        nullptr, nullptr, nullptr, nullptr, nullptr);

    // 3) h = gelu(query @ W1^T + b1) -> fp16
    gemm_h_gelu<<<dim3((2 * CDIM) / 128, MTOK / 128), 512, GT_SMEM>>>(
        pqyh, pw1h, b1, phh, 2 * CDIM, CDIM);

    // 4) fused: FFN2 GEMM + LN2(query + ff) + x -> out
    gemm_fused<1><<<MTOK / 64, 512, F_SMEM>>>(
        phh, pw2h, b2, 2 * CDIM,
        nullptr, nullptr, nullptr, nullptr, nullptr, nullptr, nullptr,
        pquery, x, ln2_w, ln2_b, out);
}

// round 16
// speedup vs baseline: 5.1165x; 1.0560x over previous
#include <cuda_runtime.h>
#include <cuda_bf16.h>
#include <cuda_fp16.h>
#include <math.h>
#include <stdint.h>

// Problem constants
#define BATCH 32
#define SEQT  1024
#define CDIM  512
#define LRAW  252
#define SLEN  128
#define MTOK  (BATCH * SEQT)   // 32768
#define LN_EPS 1e-5f

// ---------------- scratch (device globals; no allocation allowed) -------------
__device__ float g_query[MTOK * CDIM];        // LN1(q + attn_out) fp32 (residual)
__device__ float g_uk[BATCH * CDIM];
__device__ float g_uv[BATCH * CDIM];
__device__ float g_wsk[CDIM];
__device__ float g_wsv[CDIM];

// fp16 operands
__device__ uint16_t g_xh[MTOK * CDIM];            // x fp16
__device__ uint16_t g_qyh[MTOK * CDIM];           // query fp16
__device__ uint16_t g_hh[MTOK * 2 * CDIM];        // gelu out fp16
__device__ uint16_t g_wqh[CDIM * CDIM];           // Wq fp16
__device__ uint16_t g_w1h[2 * CDIM * CDIM];       // W1 fp16
__device__ uint16_t g_w2h[CDIM * 2 * CDIM];       // W2 fp16

// =============================================================================
// helpers
// =============================================================================
__device__ __forceinline__ uint32_t smem_u32(const void* p) {
    uint32_t a;
    asm("{ .reg .u64 t; cvta.to.shared.u64 t, %1; cvt.u32.u64 %0, t; }"
        : "=r"(a) : "l"(p));
    return a;
}

__device__ __forceinline__ uint32_t packh(float a, float b) {
    return (uint32_t)__half_as_ushort(__float2half(a)) |
           ((uint32_t)__half_as_ushort(__float2half(b)) << 16);
}

__device__ __forceinline__ void ldsm4(uint32_t& r0, uint32_t& r1, uint32_t& r2,
                                      uint32_t& r3, uint32_t addr) {
    asm volatile("ldmatrix.sync.aligned.m8n8.x4.shared.b16 {%0,%1,%2,%3}, [%4];"
                 : "=r"(r0), "=r"(r1), "=r"(r2), "=r"(r3) : "r"(addr));
}

__device__ __forceinline__ void mma_h(float* d, const uint32_t* a,
                                      const uint32_t* b) {
    asm volatile(
        "mma.sync.aligned.m16n8k16.row.col.f32.f16.f16.f32 "
        "{%0,%1,%2,%3}, {%4,%5,%6,%7}, {%8,%9}, {%0,%1,%2,%3};"
        : "+f"(d[0]), "+f"(d[1]), "+f"(d[2]), "+f"(d[3])
        : "r"(a[0]), "r"(a[1]), "r"(a[2]), "r"(a[3]), "r"(b[0]), "r"(b[1]));
}

__device__ __forceinline__ void cp16(uint32_t dst, const void* src) {
    asm volatile("cp.async.cg.shared.global [%0], [%1], 16;"
                 :: "r"(dst), "l"(src));
}

// =============================================================================
// FFN1 GEMM: C = A*B^T + bias, GELU, fp16 out
// CTA 128x256, K-chunk 64, 3-stage cp.async (48KB/stage), 512 thr = 16 warps
// (4m x 4n), warp tile 32x64: 6 ldsm per 16 mma.
// =============================================================================
#define F1STAGE 49152u            // A 16KB | B 32KB
#define F1NST 3
#define F1_SMEM (F1NST * F1STAGE) // 144KB

__global__ void __launch_bounds__(512, 1)
gemm_h_gelu(const uint16_t* __restrict__ Ah, const uint16_t* __restrict__ Bh,
            const float* __restrict__ bias, uint16_t* __restrict__ Ch,
            int N, int K) {
    extern __shared__ __align__(1024) char sm[];
    const uint32_t smb = smem_u32(sm);
    const int tid = threadIdx.x;
    const int wid = tid >> 5, lane = tid & 31;
    const int bn = blockIdx.x * 256;
    const int bm = blockIdx.y * 128;
    const int nc = K >> 6;

    // loader: A 1024 chunks + B 2048 chunks = 6/thread
    auto ISSUE = [&](int c) {
        const uint32_t base = smb + (c % F1NST) * F1STAGE;
        const int koff = c * 64;
#pragma unroll
        for (int i = 0; i < 6; ++i) {
            const int q = tid + 512 * i;
            if (q < 1024) {
                const int r = q >> 3, c8 = q & 7;
                const uint32_t soff = (uint32_t)r * 128u +
                    (((uint32_t)c8 * 16u) ^ (((uint32_t)r & 7u) << 4));
                cp16(base + soff, Ah + (size_t)(bm + r) * K + koff + c8 * 8);
            } else {
                const int w = q - 1024;
                const int r = w >> 3, c8 = w & 7;
                const uint32_t soff = 16384u + (uint32_t)r * 128u +
                    (((uint32_t)c8 * 16u) ^ (((uint32_t)r & 7u) << 4));
                cp16(base + soff, Bh + (size_t)(bn + r) * K + koff + c8 * 8);
            }
        }
        asm volatile("cp.async.commit_group;" ::: "memory");
    };

    const int wm = wid & 3, wn = wid >> 2;            // 4m x 4n
    const uint32_t xorm = (uint32_t)(lane & 7) << 4;
    const uint32_t rowA = (uint32_t)(wm * 32 + ((lane >> 3) & 1) * 8 + (lane & 7));
    const uint32_t kaddA = (uint32_t)(((lane >> 4) & 1) * 16);
    const uint32_t rowB = (uint32_t)(wn * 64 + ((lane >> 4) & 1) * 8 + (lane & 7));
    const uint32_t kaddB = (uint32_t)(((lane >> 3) & 1) * 16);

    float acc[2][8][4];
#pragma unroll
    for (int i = 0; i < 2; ++i)
#pragma unroll
        for (int j = 0; j < 8; ++j)
#pragma unroll
            for (int e = 0; e < 4; ++e) acc[i][j][e] = 0.f;

    auto MMA_CHUNK = [&](int s) {
        const uint32_t aB = smb + s * F1STAGE;
        const uint32_t bB = aB + 16384;
#pragma unroll
        for (int ks = 0; ks < 4; ++ks) {
            const uint32_t kb = ks * 32;
            uint32_t ah[2][4], bh[8][2];
#pragma unroll
            for (int i = 0; i < 2; ++i) {
                uint32_t off = (rowA + i * 16) * 128 + ((kb + kaddA) ^ xorm);
                ldsm4(ah[i][0], ah[i][1], ah[i][2], ah[i][3], aB + off);
            }
#pragma unroll
            for (int j2 = 0; j2 < 4; ++j2) {
                uint32_t off = (rowB + j2 * 16) * 128 + ((kb + kaddB) ^ xorm);
                ldsm4(bh[2 * j2][0], bh[2 * j2][1], bh[2 * j2 + 1][0],
                      bh[2 * j2 + 1][1], bB + off);
            }
#pragma unroll
            for (int i = 0; i < 2; ++i)
#pragma unroll
                for (int j = 0; j < 8; ++j)
                    mma_h(acc[i][j], ah[i], bh[j]);
        }
    };

    ISSUE(0);
    ISSUE(1);
    for (int c = 0; c < nc; ++c) {
        if (c + 1 < nc)
            asm volatile("cp.async.wait_group 1;" ::: "memory");
        else
            asm volatile("cp.async.wait_group 0;" ::: "memory");
        __syncthreads();
        if (c + 2 < nc) ISSUE(c + 2);
        MMA_CHUNK(c % F1NST);
    }

#pragma unroll
    for (int i = 0; i < 2; ++i) {
        const int r0 = bm + wm * 32 + i * 16 + (lane >> 2);
#pragma unroll
        for (int j = 0; j < 8; ++j) {
            const int cc = bn + wn * 64 + j * 8 + (lane & 3) * 2;
            float2 bi = *reinterpret_cast<const float2*>(bias + cc);
            float o0 = acc[i][j][0] + bi.x, o1 = acc[i][j][1] + bi.y;
            float o2 = acc[i][j][2] + bi.x, o3 = acc[i][j][3] + bi.y;
            o0 = 0.5f * o0 * (1.0f + erff(o0 * 0.7071067811865475f));
            o1 = 0.5f * o1 * (1.0f + erff(o1 * 0.7071067811865475f));
            o2 = 0.5f * o2 * (1.0f + erff(o2 * 0.7071067811865475f));
            o3 = 0.5f * o3 * (1.0f + erff(o3 * 0.7071067811865475f));
            *reinterpret_cast<uint32_t*>(Ch + (size_t)r0 * N + cc) = packh(o0, o1);
            *reinterpret_cast<uint32_t*>(Ch + (size_t)(r0 + 8) * N + cc) =
                packh(o2, o3);
        }
    }
}

// =============================================================================
// Fused full-row GEMM: CTA tile 64 x 512 (full N), 16 warps (2m x 8n),
// warp tile 32x64, K-chunk 64, 3-stage cp.async (72KB/stage).
// MODE 0: q = A*Wq^T + bq, then collapsed attention + LN1 -> query fp32 + fp16
// MODE 1: ff = A*W2^T + b2, then LN2(query + ff) + x -> out
// =============================================================================
#define FSTAGE 73728u             // A 8KB | B 64KB
#define FNST 3
#define F_SMEM (FNST * FSTAGE)    // 216KB

template <int MODE>
__global__ void __launch_bounds__(512, 1)
gemm_fused(const uint16_t* __restrict__ Ah, const uint16_t* __restrict__ Bh,
           const float* __restrict__ bias, int K,
           const float* __restrict__ bv, const float* __restrict__ conv_w,
           const float* __restrict__ conv_b, const float* __restrict__ ln1_w,
           const float* __restrict__ ln1_b, float* __restrict__ queryOut,
           uint16_t* __restrict__ qyhOut,
           const float* __restrict__ query, const float* __restrict__ xin,
           const float* __restrict__ ln2_w, const float* __restrict__ ln2_b,
           float* __restrict__ out) {
    extern __shared__ __align__(1024) char sm[];
    const uint32_t smb = smem_u32(sm);
    const int tid = threadIdx.x;
    const int wid = tid >> 5, lane = tid & 31;
    const int bm = blockIdx.x * 64;
    const int nc = K >> 6;

    auto ISSUE = [&](int c) {
        const uint32_t base = smb + (c % FNST) * FSTAGE;
        const int koff = c * 64;
        {
            const int r = tid >> 3, c8 = tid & 7;
            const uint32_t soff = (uint32_t)r * 128u +
                (((uint32_t)c8 * 16u) ^ (((uint32_t)r & 7u) << 4));
            cp16(base + soff, Ah + (size_t)(bm + r) * K + koff + c8 * 8);
        }
#pragma unroll
        for (int i = 0; i < 8; ++i) {
            const int q = tid + 512 * i;
            const int r = q >> 3, c8 = q & 7;
            const uint32_t soff = 8192u + (uint32_t)r * 128u +
                (((uint32_t)c8 * 16u) ^ (((uint32_t)r & 7u) << 4));
            cp16(base + soff, Bh + (size_t)r * K + koff + c8 * 8);
        }
        asm volatile("cp.async.commit_group;" ::: "memory");
    };

    const int wm = wid & 1, wn = wid >> 1;
    const uint32_t xorm = (uint32_t)(lane & 7) << 4;
    const uint32_t rowA = (uint32_t)(wm * 32 + ((lane >> 3) & 1) * 8 + (lane & 7));
    const uint32_t kaddA = (uint32_t)(((lane >> 4) & 1) * 16);
    const uint32_t rowB = (uint32_t)(wn * 64 + ((lane >> 4) & 1) * 8 + (lane & 7));
    const uint32_t kaddB = (uint32_t)(((lane >> 3) & 1) * 16);

    float acc[2][8][4];
#pragma unroll
    for (int i = 0; i < 2; ++i)
#pragma unroll
        for (int j = 0; j < 8; ++j)
#pragma unroll
            for (int e = 0; e < 4; ++e) acc[i][j][e] = 0.f;

    auto MMA_CHUNK = [&](int s) {
        const uint32_t aB = smb + s * FSTAGE;
        const uint32_t bB = aB + 8192;
#pragma unroll
        for (int ks = 0; ks < 4; ++ks) {
            const uint32_t kb = ks * 32;
            uint32_t ah[2][4], bh[8][2];
#pragma unroll
            for (int i = 0; i < 2; ++i) {
                uint32_t off = (rowA + i * 16) * 128 + ((kb + kaddA) ^ xorm);
                ldsm4(ah[i][0], ah[i][1], ah[i][2], ah[i][3], aB + off);
            }
#pragma unroll
            for (int j2 = 0; j2 < 4; ++j2) {
                uint32_t off = (rowB + j2 * 16) * 128 + ((kb + kaddB) ^ xorm);
                ldsm4(bh[2 * j2][0], bh[2 * j2][1], bh[2 * j2 + 1][0],
                      bh[2 * j2 + 1][1], bB + off);
            }
#pragma unroll
            for (int i = 0; i < 2; ++i)
#pragma unroll
                for (int j = 0; j < 8; ++j)
                    mma_h(acc[i][j], ah[i], bh[j]);
        }
    };

    ISSUE(0);
    ISSUE(1);
    for (int c = 0; c < nc; ++c) {
        if (c + 1 < nc)
            asm volatile("cp.async.wait_group 1;" ::: "memory");
        else
            asm volatile("cp.async.wait_group 0;" ::: "memory");
        __syncthreads();
        if (c + 2 < nc) ISSUE(c + 2);
        MMA_CHUNK(c % FNST);
    }
    __syncthreads();   // MMA done; smem reusable

    // ---- epilogue smem layout ----
    float* p = reinterpret_cast<float*>(sm);
    float* e_bias = p;
    float* e_c1   = p + 512;      // MODE0: uk   | MODE1: ln2_w
    float* e_c2   = p + 1024;     // MODE0: wsk  | MODE1: ln2_b
    float* e_c3   = p + 1536;     // MODE0: uv
    float* e_c4   = p + 2048;     // MODE0: wsv
    float* e_c5   = p + 2560;     // MODE0: bv
    float* e_c6   = p + 3072;     // MODE0: ln1_w
    float* e_c7   = p + 3584;     // MODE0: ln1_b
    float* e_cw   = p + 4096;     // 128
    float* e_cb   = p + 4224;     // 128
    float* redA   = p + 4352;     // 64 x 8
    float* redB   = p + 4864;     // 64 x 8
    float* s_al   = p + 5376;     // 64
    float* s_be   = p + 5440;     // 64
    float* s_mean = p + 5504;     // 64
    float* s_rstd = p + 5568;     // 64

    const int batch = bm >> 10;
    e_bias[tid & 511] = bias[tid & 511];
    if (MODE == 0) {
        e_c1[tid & 511] = g_uk[batch * CDIM + (tid & 511)];
        e_c2[tid & 511] = g_wsk[tid & 511];
        e_c3[tid & 511] = g_uv[batch * CDIM + (tid & 511)];
        e_c4[tid & 511] = g_wsv[tid & 511];
        e_c5[tid & 511] = bv[tid & 511];
        e_c6[tid & 511] = ln1_w[tid & 511];
        e_c7[tid & 511] = ln1_b[tid & 511];
        if (tid < SLEN) { e_cw[tid] = conv_w[tid]; e_cb[tid] = conv_b[tid]; }
    } else {
        e_c1[tid & 511] = ln2_w[tid & 511];
        e_c2[tid & 511] = ln2_b[tid & 511];
    }
    __syncthreads();

    int rl[4];
#pragma unroll
    for (int k = 0; k < 4; ++k)
        rl[k] = wm * 32 + (k >> 1) * 16 + (lane >> 2) + (k & 1) * 8;

    if (MODE == 0) {
        // ---- phase 1: q = acc + bq; partial dots q.uk, q.wsk ----
        float pA[4] = {0, 0, 0, 0}, pB[4] = {0, 0, 0, 0};
#pragma unroll
        for (int i = 0; i < 2; ++i)
#pragma unroll
            for (int j = 0; j < 8; ++j) {
                const int c0 = wn * 64 + j * 8 + (lane & 3) * 2;
                const float b0 = e_bias[c0], b1 = e_bias[c0 + 1];
                acc[i][j][0] += b0; acc[i][j][1] += b1;
                acc[i][j][2] += b0; acc[i][j][3] += b1;
                const float u0 = e_c1[c0], u1 = e_c1[c0 + 1];
                const float w0 = e_c2[c0], w1 = e_c2[c0 + 1];
                pA[2 * i]     += acc[i][j][0] * u0 + acc[i][j][1] * u1;
                pB[2 * i]     += acc[i][j][0] * w0 + acc[i][j][1] * w1;
                pA[2 * i + 1] += acc[i][j][2] * u0 + acc[i][j][3] * u1;
                pB[2 * i + 1] += acc[i][j][2] * w0 + acc[i][j][3] * w1;
            }
#pragma unroll
        for (int o = 1; o <= 2; o <<= 1)
#pragma unroll
            for (int k = 0; k < 4; ++k) {
                pA[k] += __shfl_xor_sync(0xffffffffu, pA[k], o);
                pB[k] += __shfl_xor_sync(0xffffffffu, pB[k], o);
            }
        if ((lane & 3) == 0)
#pragma unroll
            for (int k = 0; k < 4; ++k) {
                redA[rl[k] * 8 + wn] = pA[k];
                redB[rl[k] * 8 + wn] = pB[k];
            }
        __syncthreads();

        // ---- phase 2: parallel softmax, 8 threads/row x 16 s each ----
        {
            const int row = tid >> 3, seg = tid & 7;
            float A = 0.f, Bd = 0.f;
#pragma unroll
            for (int w = 0; w < 8; ++w) {
                A  += redA[row * 8 + w];
                Bd += redB[row * 8 + w];
            }
            const float scale = 0.04419417382415922f;   // 1/sqrt(512)
            float m = -1e30f;
#pragma unroll
            for (int t = 0; t < 16; ++t) {
                int s = seg * 16 + t;
                m = fmaxf(m, scale * (e_cw[s] * A + e_cb[s] * Bd));
            }
#pragma unroll
            for (int o = 1; o <= 4; o <<= 1)
                m = fmaxf(m, __shfl_xor_sync(0xffffffffu, m, o));
            float Z = 0.f, an = 0.f, bn = 0.f;
#pragma unroll
            for (int t = 0; t < 16; ++t) {
                int s = seg * 16 + t;
                float l = scale * (e_cw[s] * A + e_cb[s] * Bd);
                float e = expf(l - m);
                Z += e; an += e * e_cw[s]; bn += e * e_cb[s];
            }
#pragma unroll
            for (int o = 1; o <= 4; o <<= 1) {
                Z  += __shfl_xor_sync(0xffffffffu, Z, o);
                an += __shfl_xor_sync(0xffffffffu, an, o);
                bn += __shfl_xor_sync(0xffffffffu, bn, o);
            }
            if (seg == 0) { s_al[row] = an / Z; s_be[row] = bn / Z; }
        }
        __syncthreads();

        // ---- phase 3: y = q + alpha*uv + beta*wsv + bv; LN1 partials ----
        float pS[4] = {0, 0, 0, 0}, pQ[4] = {0, 0, 0, 0};
        float al[4], be[4];
#pragma unroll
        for (int k = 0; k < 4; ++k) { al[k] = s_al[rl[k]]; be[k] = s_be[rl[k]]; }
#pragma unroll
        for (int i = 0; i < 2; ++i)
#pragma unroll
            for (int j = 0; j < 8; ++j) {
                const int c0 = wn * 64 + j * 8 + (lane & 3) * 2;
                const float uv0 = e_c3[c0], uv1 = e_c3[c0 + 1];
                const float wv0 = e_c4[c0], wv1 = e_c4[c0 + 1];
                const float bb0 = e_c5[c0], bb1 = e_c5[c0 + 1];
                float y0 = acc[i][j][0] + al[2 * i] * uv0 + be[2 * i] * wv0 + bb0;
                float y1 = acc[i][j][1] + al[2 * i] * uv1 + be[2 * i] * wv1 + bb1;
                float y2 = acc[i][j][2] + al[2 * i + 1] * uv0 + be[2 * i + 1] * wv0 + bb0;
                float y3 = acc[i][j][3] + al[2 * i + 1] * uv1 + be[2 * i + 1] * wv1 + bb1;
                acc[i][j][0] = y0; acc[i][j][1] = y1;
                acc[i][j][2] = y2; acc[i][j][3] = y3;
                pS[2 * i]     += y0 + y1;  pQ[2 * i]     += y0 * y0 + y1 * y1;
                pS[2 * i + 1] += y2 + y3;  pQ[2 * i + 1] += y2 * y2 + y3 * y3;
            }
#pragma unroll
        for (int o = 1; o <= 2; o <<= 1)
#pragma unroll
            for (int k = 0; k < 4; ++k) {
                pS[k] += __shfl_xor_sync(0xffffffffu, pS[k], o);
                pQ[k] += __shfl_xor_sync(0xffffffffu, pQ[k], o);
            }
        if ((lane & 3) == 0)
#pragma unroll
            for (int k = 0; k < 4; ++k) {
                redA[rl[k] * 8 + wn] = pS[k];
                redB[rl[k] * 8 + wn] = pQ[k];
            }
        __syncthreads();
        if (tid < 64) {
            float s = 0.f, q2 = 0.f;
#pragma unroll
            for (int w = 0; w < 8; ++w) { s += redA[tid * 8 + w]; q2 += redB[tid * 8 + w]; }
            const float mean = s * (1.f / 512.f);
            const float var  = q2 * (1.f / 512.f) - mean * mean;
            s_mean[tid] = mean;
            s_rstd[tid] = rsqrtf(var + LN_EPS);
        }
        __syncthreads();

        // ---- phase 4: write query fp32 + fp16 ----
        float mn[4], rs[4];
#pragma unroll
        for (int k = 0; k < 4; ++k) { mn[k] = s_mean[rl[k]]; rs[k] = s_rstd[rl[k]]; }
#pragma unroll
        for (int i = 0; i < 2; ++i)
#pragma unroll
            for (int j = 0; j < 8; ++j) {
                const int c0 = wn * 64 + j * 8 + (lane & 3) * 2;
                const float lw0 = e_c6[c0], lw1 = e_c6[c0 + 1];
                const float lb0 = e_c7[c0], lb1 = e_c7[c0 + 1];
                const int g0 = bm + rl[2 * i], g1 = bm + rl[2 * i + 1];
                float o0 = (acc[i][j][0] - mn[2 * i]) * rs[2 * i] * lw0 + lb0;
                float o1 = (acc[i][j][1] - mn[2 * i]) * rs[2 * i] * lw1 + lb1;
                float o2 = (acc[i][j][2] - mn[2 * i + 1]) * rs[2 * i + 1] * lw0 + lb0;
                float o3 = (acc[i][j][3] - mn[2 * i + 1]) * rs[2 * i + 1] * lw1 + lb1;
                *reinterpret_cast<float2*>(queryOut + (size_t)g0 * CDIM + c0) =
                    make_float2(o0, o1);
                *reinterpret_cast<float2*>(queryOut + (size_t)g1 * CDIM + c0) =
                    make_float2(o2, o3);
                *reinterpret_cast<uint32_t*>(qyhOut + (size_t)g0 * CDIM + c0) =
                    packh(o0, o1);
                *reinterpret_cast<uint32_t*>(qyhOut + (size_t)g1 * CDIM + c0) =
                    packh(o2, o3);
            }
    } else {
        // ---- MODE 1: ff = acc + b2; y = query + ff; LN2; + x -> out ----
        float pS[4] = {0, 0, 0, 0}, pQ[4] = {0, 0, 0, 0};
#pragma unroll
        for (int i = 0; i < 2; ++i)
#pragma unroll
            for (int j = 0; j < 8; ++j) {
                const int c0 = wn * 64 + j * 8 + (lane & 3) * 2;
                const float b0 = e_bias[c0], b1 = e_bias[c0 + 1];
                const int g0 = bm + rl[2 * i], g1 = bm + rl[2 * i + 1];
                float2 q0 = *reinterpret_cast<const float2*>(
                    query + (size_t)g0 * CDIM + c0);
                float2 q1 = *reinterpret_cast<const float2*>(
                    query + (size_t)g1 * CDIM + c0);
                float y0 = acc[i][j][0] + b0 + q0.x;
                float y1 = acc[i][j][1] + b1 + q0.y;
                float y2 = acc[i][j][2] + b0 + q1.x;
                float y3 = acc[i][j][3] + b1 + q1.y;
                acc[i][j][0] = y0; acc[i][j][1] = y1;
                acc[i][j][2] = y2; acc[i][j][3] = y3;
                pS[2 * i]     += y0 + y1;  pQ[2 * i]     += y0 * y0 + y1 * y1;
                pS[2 * i + 1] += y2 + y3;  pQ[2 * i + 1] += y2 * y2 + y3 * y3;
            }
#pragma unroll
        for (int o = 1; o <= 2; o <<= 1)
#pragma unroll
            for (int k = 0; k < 4; ++k) {
                pS[k] += __shfl_xor_sync(0xffffffffu, pS[k], o);
                pQ[k] += __shfl_xor_sync(0xffffffffu, pQ[k], o);
            }
        if ((lane & 3) == 0)
#pragma unroll
            for (int k = 0; k < 4; ++k) {
                redA[rl[k] * 8 + wn] = pS[k];
                redB[rl[k] * 8 + wn] = pQ[k];
            }
        __syncthreads();
        if (tid < 64) {
            float s = 0.f, q2 = 0.f;
#pragma unroll
            for (int w = 0; w < 8; ++w) { s += redA[tid * 8 + w]; q2 += redB[tid * 8 + w]; }
            const float mean = s * (1.f / 512.f);
            const float var  = q2 * (1.f / 512.f) - mean * mean;
            s_mean[tid] = mean;
            s_rstd[tid] = rsqrtf(var + LN_EPS);
        }
        __syncthreads();

        float mn[4], rs[4];
#pragma unroll
        for (int k = 0; k < 4; ++k) { mn[k] = s_mean[rl[k]]; rs[k] = s_rstd[rl[k]]; }
#pragma unroll
        for (int i = 0; i < 2; ++i)
#pragma unroll
            for (int j = 0; j < 8; ++j) {
                const int c0 = wn * 64 + j * 8 + (lane & 3) * 2;
                const float lw0 = e_c1[c0], lw1 = e_c1[c0 + 1];
                const float lb0 = e_c2[c0], lb1 = e_c2[c0 + 1];
                const int g0 = bm + rl[2 * i], g1 = bm + rl[2 * i + 1];
                float2 x0 = *reinterpret_cast<const float2*>(
                    xin + (size_t)g0 * CDIM + c0);
                float2 x1 = *reinterpret_cast<const float2*>(
                    xin + (size_t)g1 * CDIM + c0);
                float o0 = (acc[i][j][0] - mn[2 * i]) * rs[2 * i] * lw0 + lb0 + x0.x;
                float o1 = (acc[i][j][1] - mn[2 * i]) * rs[2 * i] * lw1 + lb1 + x0.y;
                float o2 = (acc[i][j][2] - mn[2 * i + 1]) * rs[2 * i + 1] * lw0 + lb0 + x1.x;
                float o3 = (acc[i][j][3] - mn[2 * i + 1]) * rs[2 * i + 1] * lw1 + lb1 + x1.y;
                *reinterpret_cast<float2*>(out + (size_t)g0 * CDIM + c0) =
                    make_float2(o0, o1);
                *reinterpret_cast<float2*>(out + (size_t)g1 * CDIM + c0) =
                    make_float2(o2, o3);
            }
    }
}

// ---------------- fp32 -> fp16 convert (stream) -------------------------------
__global__ void cvt_h_kernel(const float4* __restrict__ src, uint2* __restrict__ dst,
                             int n4) {
    int i = blockIdx.x * 256 + threadIdx.x;
    if (i < n4) {
        float4 v = src[i];
        uint2 o;
        o.x = packh(v.x, v.y);
        o.y = packh(v.z, v.w);
        dst[i] = o;
    }
}

// ---------------- prep: u_k, u_v, wsum_k, wsum_v ------------------------------
__global__ void prep_kernel(const float* __restrict__ cond_emb,
                            const float* __restrict__ Wk,
                            const float* __restrict__ Wv) {
    __shared__ __align__(16) float s_pad[256];
    int b = blockIdx.x;
    int t = threadIdx.x;
    if (t < 256) {
        int src = (t + 250) % 252;              // (t - 2) mod 252
        s_pad[t] = cond_emb[b * LRAW + src];
    }
    __syncthreads();
    int n = t;
    const float4* wk4 = reinterpret_cast<const float4*>(Wk + (size_t)n * 256);
    const float4* wv4 = reinterpret_cast<const float4*>(Wv + (size_t)n * 256);
    const float4* p4  = reinterpret_cast<const float4*>(s_pad);
    float uk = 0.f, uv = 0.f, sk = 0.f, sv = 0.f;
#pragma unroll 8
    for (int c = 0; c < 64; c++) {
        float4 p = p4[c];
        float4 k = wk4[c];
        float4 v = wv4[c];
        uk += p.x * k.x + p.y * k.y + p.z * k.z + p.w * k.w;
        uv += p.x * v.x + p.y * v.y + p.z * v.z + p.w * v.w;
        sk += k.x + k.y + k.z + k.w;
        sv += v.x + v.y + v.z + v.w;
    }
    g_uk[b * CDIM + n] = uk;
    g_uv[b * CDIM + n] = uv;
    if (b == 0) { g_wsk[n] = sk; g_wsv[n] = sv; }
}

// ---------------- launch ------------------------------------------------------
extern "C" void kernel_launch(void* const* d_in, const int* in_sizes, int n_in,
                              void* d_out, int out_size) {
    const float* x        = (const float*)d_in[0];
    const float* cond_emb = (const float*)d_in[1];
    const float* Wq       = (const float*)d_in[2];
    const float* bq       = (const float*)d_in[3];
    const float* Wk       = (const float*)d_in[4];
    // d_in[5] = bk: constant shift along s, cancels in softmax
    const float* Wv       = (const float*)d_in[6];
    const float* bv       = (const float*)d_in[7];
    const float* conv_w   = (const float*)d_in[8];
    const float* conv_b   = (const float*)d_in[9];
    const float* ln1_w    = (const float*)d_in[10];
    const float* ln1_b    = (const float*)d_in[11];
    const float* W1       = (const float*)d_in[12];
    const float* b1       = (const float*)d_in[13];
    const float* W2       = (const float*)d_in[14];
    const float* b2       = (const float*)d_in[15];
    const float* ln2_w    = (const float*)d_in[16];
    const float* ln2_b    = (const float*)d_in[17];
    float* out            = (float*)d_out;

    float* pquery;
    cudaGetSymbolAddress((void**)&pquery, g_query);
    uint16_t *pxh, *pqyh, *phh, *pwqh, *pw1h, *pw2h;
    cudaGetSymbolAddress((void**)&pxh, g_xh);
    cudaGetSymbolAddress((void**)&pqyh, g_qyh);
    cudaGetSymbolAddress((void**)&phh, g_hh);
    cudaGetSymbolAddress((void**)&pwqh, g_wqh);
    cudaGetSymbolAddress((void**)&pw1h, g_w1h);
    cudaGetSymbolAddress((void**)&pw2h, g_w2h);

    cudaFuncSetAttribute(gemm_h_gelu, cudaFuncAttributeMaxDynamicSharedMemorySize,
                         F1_SMEM);
    cudaFuncSetAttribute(gemm_fused<0>,
                         cudaFuncAttributeMaxDynamicSharedMemorySize, F_SMEM);
    cudaFuncSetAttribute(gemm_fused<1>,
                         cudaFuncAttributeMaxDynamicSharedMemorySize, F_SMEM);

    // 0) operand prep (fp32 -> fp16)
    cvt_h_kernel<<<(MTOK * CDIM / 4 + 255) / 256, 256>>>(
        (const float4*)x, (uint2*)pxh, MTOK * CDIM / 4);
    cvt_h_kernel<<<(CDIM * CDIM / 4 + 255) / 256, 256>>>(
        (const float4*)Wq, (uint2*)pwqh, CDIM * CDIM / 4);
    cvt_h_kernel<<<(2 * CDIM * CDIM / 4 + 255) / 256, 256>>>(
        (const float4*)W1, (uint2*)pw1h, 2 * CDIM * CDIM / 4);
    cvt_h_kernel<<<(2 * CDIM * CDIM / 4 + 255) / 256, 256>>>(
        (const float4*)W2, (uint2*)pw2h, 2 * CDIM * CDIM / 4);

    // 1) conditioner factorization
    prep_kernel<<<BATCH, 512>>>(cond_emb, Wk, Wv);

    // 2) fused: q GEMM + collapsed attention + LN1 -> query (fp32 + fp16)
    gemm_fused<0><<<MTOK / 64, 512, F_SMEM>>>(
        pxh, pwqh, bq, CDIM,
        bv, conv_w, conv_b, ln1_w, ln1_b, pquery, pqyh,
        nullptr, nullptr, nullptr, nullptr, nullptr);

    // 3) h = gelu(query @ W1^T + b1) -> fp16  [tile 128x256]
    gemm_h_gelu<<<dim3((2 * CDIM) / 256, MTOK / 128), 512, F1_SMEM>>>(
        pqyh, pw1h, b1, phh, 2 * CDIM, CDIM);

    // 4) fused: FFN2 GEMM + LN2(query + ff) + x -> out
    gemm_fused<1><<<MTOK / 64, 512, F_SMEM>>>(
        phh, pw2h, b2, 2 * CDIM,
        nullptr, nullptr, nullptr, nullptr, nullptr, nullptr, nullptr,
        pquery, x, ln2_w, ln2_b, out);
}